// round 4
// baseline (speedup 1.0000x reference)
#include <cuda_runtime.h>
#include <math.h>

#define NODE_DIM 128
#define MAX_NODES 100000

typedef unsigned long long u64;

// Scratch: per-node precomputed UV[n] = [u[n] (128) | v[n] (128)]
__device__ float g_UV[(size_t)MAX_NODES * 256];

// ---------------------------------------------------------------------------
// Packed f32x2 helpers (sm_103a FFMA2 — PTX-only, ptxas won't auto-fuse)
// ---------------------------------------------------------------------------
__device__ __forceinline__ u64 pack2(float x, float y) {
    u64 r;
    asm("mov.b64 %0, {%1, %2};" : "=l"(r) : "f"(x), "f"(y));
    return r;
}
__device__ __forceinline__ u64 fma2(u64 a, u64 b, u64 c) {
    u64 d;
    asm("fma.rn.f32x2 %0, %1, %2, %3;" : "=l"(d) : "l"(a), "l"(b), "l"(c));
    return d;
}
__device__ __forceinline__ float2 unpack2(u64 v) {
    float2 r;
    asm("mov.b64 {%0, %1}, %2;" : "=f"(r.x), "=f"(r.y) : "l"(v));
    return r;
}

// ---------------------------------------------------------------------------
// GEMM: UV[N, 256] = x[N, 128] @ Wcat[128, 256], packed f32x2, zero inner movs.
// blockIdx.y selects the W1 half. Tile 128x128x16, 256 threads, 8x8 microtile.
//  sA: [k][m] u64 with each entry = (a,a) duplicated pair  (16 KB)
//  sB: [k][j] u64 with entry j = cols (2j, 2j+1)           ( 8 KB)
// ---------------------------------------------------------------------------
#define BM 128
#define BK 16

__global__ void __launch_bounds__(256, 2) gemm_uv_kernel(
    const float* __restrict__ x, const float* __restrict__ W1, int N)
{
    __shared__ __align__(16) u64 sA[BK][BM];
    __shared__ __align__(16) u64 sB[BK][64];

    const int row0 = blockIdx.x * BM;
    const int col0 = blockIdx.y * NODE_DIM;             // 0 or 128 in UV
    const float* Wb = W1 + (size_t)blockIdx.y * NODE_DIM * NODE_DIM;

    const int tid = threadIdx.x;
    const int tx = tid & 15;    // col group: cols tx*4..+3 and 64+tx*4..+3
    const int ty = tid >> 4;    // row group: rows {rh*64} + ty*4..+3

    // acc[rh][i][j]: row rh*64+ty*4+i, col pair j (j<2: tx*4+2j ; j>=2: 64+tx*4+2(j-2))
    u64 acc[2][4][4];
#pragma unroll
    for (int rh = 0; rh < 2; ++rh)
#pragma unroll
        for (int i = 0; i < 4; ++i)
#pragma unroll
            for (int j = 0; j < 4; ++j) acc[rh][i][j] = 0ull;

    for (int k0 = 0; k0 < NODE_DIM; k0 += BK) {
        // A tile: 128 rows x 16 k. Each thread: 2 float4 loads, scatter as dup pairs.
#pragma unroll
        for (int t = 0; t < 2; ++t) {
            int idx = t * 256 + tid;
            int r  = idx >> 2;          // 0..127
            int c4 = idx & 3;           // float4 index along k
            float4 xv = make_float4(0.f, 0.f, 0.f, 0.f);
            int gr = row0 + r;
            if (gr < N) xv = *(const float4*)&x[(size_t)gr * NODE_DIM + k0 + c4 * 4];
            sA[c4 * 4 + 0][r] = pack2(xv.x, xv.x);
            sA[c4 * 4 + 1][r] = pack2(xv.y, xv.y);
            sA[c4 * 4 + 2][r] = pack2(xv.z, xv.z);
            sA[c4 * 4 + 3][r] = pack2(xv.w, xv.w);
        }
        // B tile: 16 k x 128 n. float4 store == two col-pair u64s (same bits).
#pragma unroll
        for (int t = 0; t < 2; ++t) {
            int idx = t * 256 + tid;
            int kk = idx >> 5;          // 0..15
            int c4 = idx & 31;          // 0..31
            float4 wv = *(const float4*)&Wb[(size_t)(k0 + kk) * NODE_DIM + c4 * 4];
            *(float4*)&sB[kk][c4 * 2] = wv;
        }
        __syncthreads();

#pragma unroll
        for (int k = 0; k < BK; ++k) {
            ulonglong2 b0 = *(const ulonglong2*)&sB[k][tx * 2];       // cols tx*4..+3
            ulonglong2 b1 = *(const ulonglong2*)&sB[k][32 + tx * 2];  // cols 64+tx*4..+3
#pragma unroll
            for (int rh = 0; rh < 2; ++rh) {
                int rbase = rh * 64 + ty * 4;
                ulonglong2 a01 = *(const ulonglong2*)&sA[k][rbase];
                ulonglong2 a23 = *(const ulonglong2*)&sA[k][rbase + 2];
                acc[rh][0][0] = fma2(a01.x, b0.x, acc[rh][0][0]);
                acc[rh][0][1] = fma2(a01.x, b0.y, acc[rh][0][1]);
                acc[rh][0][2] = fma2(a01.x, b1.x, acc[rh][0][2]);
                acc[rh][0][3] = fma2(a01.x, b1.y, acc[rh][0][3]);
                acc[rh][1][0] = fma2(a01.y, b0.x, acc[rh][1][0]);
                acc[rh][1][1] = fma2(a01.y, b0.y, acc[rh][1][1]);
                acc[rh][1][2] = fma2(a01.y, b1.x, acc[rh][1][2]);
                acc[rh][1][3] = fma2(a01.y, b1.y, acc[rh][1][3]);
                acc[rh][2][0] = fma2(a23.x, b0.x, acc[rh][2][0]);
                acc[rh][2][1] = fma2(a23.x, b0.y, acc[rh][2][1]);
                acc[rh][2][2] = fma2(a23.x, b1.x, acc[rh][2][2]);
                acc[rh][2][3] = fma2(a23.x, b1.y, acc[rh][2][3]);
                acc[rh][3][0] = fma2(a23.y, b0.x, acc[rh][3][0]);
                acc[rh][3][1] = fma2(a23.y, b0.y, acc[rh][3][1]);
                acc[rh][3][2] = fma2(a23.y, b1.x, acc[rh][3][2]);
                acc[rh][3][3] = fma2(a23.y, b1.y, acc[rh][3][3]);
            }
        }
        __syncthreads();
    }

    // Store to g_UV (row stride 256; this block's cols [col0, col0+128))
#pragma unroll
    for (int rh = 0; rh < 2; ++rh) {
#pragma unroll
        for (int i = 0; i < 4; ++i) {
            int gr = row0 + rh * 64 + ty * 4 + i;
            if (gr < N) {
                float2 p0 = unpack2(acc[rh][i][0]);
                float2 p1 = unpack2(acc[rh][i][1]);
                float2 p2 = unpack2(acc[rh][i][2]);
                float2 p3 = unpack2(acc[rh][i][3]);
                *(float4*)&g_UV[(size_t)gr * 256 + col0 + tx * 4] =
                    make_float4(p0.x, p0.y, p1.x, p1.y);
                *(float4*)&g_UV[(size_t)gr * 256 + col0 + 64 + tx * 4] =
                    make_float4(p2.x, p2.y, p3.x, p3.y);
            }
        }
    }
}

// ---------------------------------------------------------------------------
// Edge pass: one warp per edge, with inline edge-index dtype detection.
//   h = relu(u[src] + v[dst] + b1);  out = sigmoid(h . W2 + b2)
// Detection: reinterpret first 16 slots as int64; with int32 data the paired
// values are out of [0,N) w.p. ~1. One L2-hot load + ballot per warp.
// ---------------------------------------------------------------------------
__global__ void __launch_bounds__(256) edge_kernel(
    const void* __restrict__ ei_raw,
    const float* __restrict__ b1,
    const float* __restrict__ W2,
    const float* __restrict__ b2,
    float* __restrict__ out, int E, int N)
{
    int warp = (int)((blockIdx.x * blockDim.x + threadIdx.x) >> 5);
    int lane = threadIdx.x & 31;

    const long long* p64 = (const long long*)ei_raw;
    long long probe = __ldg(&p64[lane & 15]);
    bool ok = (probe >= 0 && probe < (long long)N);
    bool is64 = (__ballot_sync(0xffffffffu, ok) == 0xffffffffu);

    if (warp >= E) return;

    long long s, d;
    if (is64) {
        s = __ldg(&p64[warp]);
        d = __ldg(&p64[(size_t)E + warp]);
    } else {
        const int* ei = (const int*)ei_raw;
        s = __ldg(&ei[warp]);
        d = __ldg(&ei[(size_t)E + warp]);
    }
    // Safety clamp: never fault even if detection were wrong.
    if (s < 0) s = 0; if (s >= N) s = N - 1;
    if (d < 0) d = 0; if (d >= N) d = N - 1;

    float4 u = *(const float4*)&g_UV[(size_t)s * 256 + lane * 4];
    float4 v = *(const float4*)&g_UV[(size_t)d * 256 + 128 + lane * 4];
    float4 bb = __ldg((const float4*)b1 + lane);
    float4 w  = __ldg((const float4*)W2 + lane);

    float h0 = fmaxf(u.x + v.x + bb.x, 0.0f);
    float h1 = fmaxf(u.y + v.y + bb.y, 0.0f);
    float h2 = fmaxf(u.z + v.z + bb.z, 0.0f);
    float h3 = fmaxf(u.w + v.w + bb.w, 0.0f);

    float p = h0 * w.x + h1 * w.y + h2 * w.z + h3 * w.w;
#pragma unroll
    for (int off = 16; off > 0; off >>= 1)
        p += __shfl_xor_sync(0xffffffffu, p, off);

    if (lane == 0) {
        float z = p + __ldg(b2);
        out[warp] = 1.0f / (1.0f + expf(-z));
    }
}

// ---------------------------------------------------------------------------
extern "C" void kernel_launch(void* const* d_in, const int* in_sizes, int n_in,
                              void* d_out, int out_size)
{
    const float* x   = (const float*)d_in[0];
    const void*  ei  = d_in[1];
    const float* W1  = (const float*)d_in[2];
    const float* b1  = (const float*)d_in[3];
    const float* W2  = (const float*)d_in[4];
    const float* b2  = (const float*)d_in[5];
    float* out = (float*)d_out;

    int N = in_sizes[0] / NODE_DIM;   // 100000
    int E = in_sizes[1] / 2;          // 600000

    dim3 ggrid((N + BM - 1) / BM, 2);
    gemm_uv_kernel<<<ggrid, 256>>>(x, W1, N);

    long long total_threads = (long long)E * 32;
    int blocks = (int)((total_threads + 255) / 256);
    edge_kernel<<<blocks, 256>>>(ei, b1, W2, b2, out, E, N);
}

// round 5
// speedup vs baseline: 1.0655x; 1.0655x over previous
#include <cuda_runtime.h>
#include <math.h>

#define NODE_DIM 128
#define MAX_NODES 100000

typedef unsigned long long u64;

// Scratch: per-node precomputed UV[n] = [u[n] (128) | v[n] (128)]
__device__ float g_UV[(size_t)MAX_NODES * 256];

// ---------------------------------------------------------------------------
// Packed f32x2 helpers (sm_103a FFMA2 — PTX-only, ptxas won't auto-fuse)
// ---------------------------------------------------------------------------
__device__ __forceinline__ u64 pack2(float x, float y) {
    u64 r;
    asm("mov.b64 %0, {%1, %2};" : "=l"(r) : "f"(x), "f"(y));
    return r;
}
__device__ __forceinline__ u64 fma2(u64 a, u64 b, u64 c) {
    u64 d;
    asm("fma.rn.f32x2 %0, %1, %2, %3;" : "=l"(d) : "l"(a), "l"(b), "l"(c));
    return d;
}
__device__ __forceinline__ float2 unpack2(u64 v) {
    float2 r;
    asm("mov.b64 {%0, %1}, %2;" : "=f"(r.x), "=f"(r.y) : "l"(v));
    return r;
}

// ---------------------------------------------------------------------------
// GEMM: UV[N, 256] = x[N, 128] @ Wcat[128, 256], packed f32x2, zero inner movs.
// blockIdx.y selects the W1 half. Tile 128x128x16, 256 threads, 8x8 microtile.
//  sA: [k][m] u64, entry = (a,a) dup pair, row padded +2 (2-way store conflicts)
//  sB: [k][j] u64, entry j = cols (2j, 2j+1)
// ---------------------------------------------------------------------------
#define BM 128
#define BK 16
#define AP (BM + 2)   // padded sA row length in u64

__global__ void __launch_bounds__(256, 2) gemm_uv_kernel(
    const float* __restrict__ x, const float* __restrict__ W1, int N)
{
    __shared__ __align__(16) u64 sA[BK * AP];
    __shared__ __align__(16) u64 sB[BK][64];

    const int row0 = blockIdx.x * BM;
    const int col0 = blockIdx.y * NODE_DIM;             // 0 or 128 in UV
    const float* Wb = W1 + (size_t)blockIdx.y * NODE_DIM * NODE_DIM;

    const int tid = threadIdx.x;
    const int tx = tid & 15;    // col group: cols tx*4..+3 and 64+tx*4..+3
    const int ty = tid >> 4;    // row group: rows {rh*64} + ty*4..+3

    u64 acc[2][4][4];
#pragma unroll
    for (int rh = 0; rh < 2; ++rh)
#pragma unroll
        for (int i = 0; i < 4; ++i)
#pragma unroll
            for (int j = 0; j < 4; ++j) acc[rh][i][j] = 0ull;

    for (int k0 = 0; k0 < NODE_DIM; k0 += BK) {
        // A tile: 128 rows x 16 k. Coalesced float4 loads (4 lanes/row),
        // scattered as dup pairs into transposed padded layout.
#pragma unroll
        for (int t = 0; t < 2; ++t) {
            int idx = t * 256 + tid;
            int r  = idx >> 2;          // 0..127
            int c4 = idx & 3;           // float4 index along k
            float4 xv = make_float4(0.f, 0.f, 0.f, 0.f);
            int gr = row0 + r;
            if (gr < N) xv = *(const float4*)&x[(size_t)gr * NODE_DIM + k0 + c4 * 4];
            sA[(c4 * 4 + 0) * AP + r] = pack2(xv.x, xv.x);
            sA[(c4 * 4 + 1) * AP + r] = pack2(xv.y, xv.y);
            sA[(c4 * 4 + 2) * AP + r] = pack2(xv.z, xv.z);
            sA[(c4 * 4 + 3) * AP + r] = pack2(xv.w, xv.w);
        }
        // B tile: 16 k x 128 n. float4 store == two col-pair u64s (same bits).
#pragma unroll
        for (int t = 0; t < 2; ++t) {
            int idx = t * 256 + tid;
            int kk = idx >> 5;          // 0..15
            int c4 = idx & 31;          // 0..31
            float4 wv = *(const float4*)&Wb[(size_t)(k0 + kk) * NODE_DIM + c4 * 4];
            *(float4*)&sB[kk][c4 * 2] = wv;
        }
        __syncthreads();

#pragma unroll
        for (int k = 0; k < BK; ++k) {
            ulonglong2 b0 = *(const ulonglong2*)&sB[k][tx * 2];       // cols tx*4..+3
            ulonglong2 b1 = *(const ulonglong2*)&sB[k][32 + tx * 2];  // cols 64+tx*4..+3
#pragma unroll
            for (int rh = 0; rh < 2; ++rh) {
                int rbase = rh * 64 + ty * 4;
                ulonglong2 a01 = *(const ulonglong2*)&sA[k * AP + rbase];
                ulonglong2 a23 = *(const ulonglong2*)&sA[k * AP + rbase + 2];
                acc[rh][0][0] = fma2(a01.x, b0.x, acc[rh][0][0]);
                acc[rh][0][1] = fma2(a01.x, b0.y, acc[rh][0][1]);
                acc[rh][0][2] = fma2(a01.x, b1.x, acc[rh][0][2]);
                acc[rh][0][3] = fma2(a01.x, b1.y, acc[rh][0][3]);
                acc[rh][1][0] = fma2(a01.y, b0.x, acc[rh][1][0]);
                acc[rh][1][1] = fma2(a01.y, b0.y, acc[rh][1][1]);
                acc[rh][1][2] = fma2(a01.y, b1.x, acc[rh][1][2]);
                acc[rh][1][3] = fma2(a01.y, b1.y, acc[rh][1][3]);
                acc[rh][2][0] = fma2(a23.x, b0.x, acc[rh][2][0]);
                acc[rh][2][1] = fma2(a23.x, b0.y, acc[rh][2][1]);
                acc[rh][2][2] = fma2(a23.x, b1.x, acc[rh][2][2]);
                acc[rh][2][3] = fma2(a23.x, b1.y, acc[rh][2][3]);
                acc[rh][3][0] = fma2(a23.y, b0.x, acc[rh][3][0]);
                acc[rh][3][1] = fma2(a23.y, b0.y, acc[rh][3][1]);
                acc[rh][3][2] = fma2(a23.y, b1.x, acc[rh][3][2]);
                acc[rh][3][3] = fma2(a23.y, b1.y, acc[rh][3][3]);
            }
        }
        __syncthreads();
    }

    // Store to g_UV (row stride 256; this block's cols [col0, col0+128))
#pragma unroll
    for (int rh = 0; rh < 2; ++rh) {
#pragma unroll
        for (int i = 0; i < 4; ++i) {
            int gr = row0 + rh * 64 + ty * 4 + i;
            if (gr < N) {
                float2 p0 = unpack2(acc[rh][i][0]);
                float2 p1 = unpack2(acc[rh][i][1]);
                float2 p2 = unpack2(acc[rh][i][2]);
                float2 p3 = unpack2(acc[rh][i][3]);
                *(float4*)&g_UV[(size_t)gr * 256 + col0 + tx * 4] =
                    make_float4(p0.x, p0.y, p1.x, p1.y);
                *(float4*)&g_UV[(size_t)gr * 256 + col0 + 64 + tx * 4] =
                    make_float4(p2.x, p2.y, p3.x, p3.y);
            }
        }
    }
}

// ---------------------------------------------------------------------------
// Edge pass: one warp per edge, inline dtype detection, 32-bit UV indexing.
//   h = relu(u[src] + v[dst] + b1);  out = sigmoid(h . W2 + b2)
// ---------------------------------------------------------------------------
__global__ void __launch_bounds__(256) edge_kernel(
    const void* __restrict__ ei_raw,
    const float* __restrict__ b1,
    const float* __restrict__ W2,
    const float* __restrict__ b2,
    float* __restrict__ out, int E, int N)
{
    int warp = (int)((blockIdx.x * blockDim.x + threadIdx.x) >> 5);
    int lane = threadIdx.x & 31;

    const long long* p64 = (const long long*)ei_raw;
    long long probe = __ldg(&p64[lane & 15]);
    bool ok = (probe >= 0 && probe < (long long)N);
    bool is64 = (__ballot_sync(0xffffffffu, ok) == 0xffffffffu);

    if (warp >= E) return;

    int s, d;
    if (is64) {
        s = (int)__ldg(&p64[warp]);
        d = (int)__ldg(&p64[(size_t)E + warp]);
    } else {
        const int* ei = (const int*)ei_raw;
        s = __ldg(&ei[warp]);
        d = __ldg(&ei[(size_t)E + warp]);
    }
    // Safety clamp: never fault even if detection were wrong.
    s = min(max(s, 0), N - 1);
    d = min(max(d, 0), N - 1);

    // 32-bit offsets: max index 100000*256 + 252 < 2^25
    unsigned ub = (unsigned)s * 256u + (unsigned)(lane * 4);
    unsigned vb = (unsigned)d * 256u + 128u + (unsigned)(lane * 4);
    float4 u = *(const float4*)&g_UV[ub];
    float4 v = *(const float4*)&g_UV[vb];
    float4 bb = __ldg((const float4*)b1 + lane);
    float4 w  = __ldg((const float4*)W2 + lane);

    float h0 = fmaxf(u.x + v.x + bb.x, 0.0f);
    float h1 = fmaxf(u.y + v.y + bb.y, 0.0f);
    float h2 = fmaxf(u.z + v.z + bb.z, 0.0f);
    float h3 = fmaxf(u.w + v.w + bb.w, 0.0f);

    float p = fmaf(h0, w.x, fmaf(h1, w.y, fmaf(h2, w.z, h3 * w.w)));
#pragma unroll
    for (int off = 16; off > 0; off >>= 1)
        p += __shfl_xor_sync(0xffffffffu, p, off);

    if (lane == 0) {
        float z = p + __ldg(b2);
        out[warp] = 1.0f / (1.0f + expf(-z));
    }
}

// ---------------------------------------------------------------------------
extern "C" void kernel_launch(void* const* d_in, const int* in_sizes, int n_in,
                              void* d_out, int out_size)
{
    const float* x   = (const float*)d_in[0];
    const void*  ei  = d_in[1];
    const float* W1  = (const float*)d_in[2];
    const float* b1  = (const float*)d_in[3];
    const float* W2  = (const float*)d_in[4];
    const float* b2  = (const float*)d_in[5];
    float* out = (float*)d_out;

    int N = in_sizes[0] / NODE_DIM;   // 100000
    int E = in_sizes[1] / 2;          // 600000

    dim3 ggrid((N + BM - 1) / BM, 2);
    gemm_uv_kernel<<<ggrid, 256>>>(x, W1, N);

    long long total_threads = (long long)E * 32;
    int blocks = (int)((total_threads + 255) / 256);
    edge_kernel<<<blocks, 256>>>(ei, b1, W2, b2, out, E, N);
}

// round 8
// speedup vs baseline: 1.3792x; 1.2945x over previous
#include <cuda_runtime.h>
#include <cuda_bf16.h>
#include <math.h>
#include <string.h>

#define NODE_DIM 128
#define MAX_NODES 100000

typedef unsigned long long u64;
typedef unsigned int u32;

// Scratch: per-node precomputed UV[n] = [u[n] (128) | v[n] (128)]
__device__ float g_UV[(size_t)MAX_NODES * 256];

// ---------------------------------------------------------------------------
// SMEM layout (dynamic, bytes). Rows padded to 136 bf16 (272 B) so ldmatrix
// 8-row groups hit distinct banks (272/4 = 68 ≡ 4 mod 32).
//  A: 128 rows x 136 -> 34816 B per copy (hi, lo)
//  B: 256 rows x 136 -> 69632 B per copy (hi, lo), B[n][k] = Wcat[k][n]
// ---------------------------------------------------------------------------
#define KP 136
#define SM_AHI 0
#define SM_ALO 34816
#define SM_BHI 69632
#define SM_BLO 139264
#define SM_TOTAL 208896

#define LDSM_X4(r0, r1, r2, r3, addr) \
    asm volatile("ldmatrix.sync.aligned.m8n8.x4.shared.b16 {%0,%1,%2,%3}, [%4];" \
                 : "=r"(r0), "=r"(r1), "=r"(r2), "=r"(r3) : "r"(addr))

#define MMA16816(c, a, b) \
    asm volatile("mma.sync.aligned.m16n8k16.row.col.f32.bf16.bf16.f32 " \
                 "{%0,%1,%2,%3}, {%4,%5,%6,%7}, {%8,%9}, {%0,%1,%2,%3};" \
                 : "+f"((c)[0]), "+f"((c)[1]), "+f"((c)[2]), "+f"((c)[3]) \
                 : "r"((a)[0]), "r"((a)[1]), "r"((a)[2]), "r"((a)[3]), \
                   "r"((b)[0]), "r"((b)[1]))

__device__ __forceinline__ u32 smem_u32(const void* p) {
    u32 a;
    asm("{ .reg .u64 t; cvta.to.shared.u64 t, %1; cvt.u32.u64 %0, t; }" : "=r"(a) : "l"(p));
    return a;
}
__device__ __forceinline__ u32 bf2_u32(__nv_bfloat162 v) {
    u32 u; memcpy(&u, &v, 4); return u;
}
__device__ __forceinline__ u64 hi4(float a, float b, float c, float d) {
    return (u64)bf2_u32(__floats2bfloat162_rn(a, b))
         | ((u64)bf2_u32(__floats2bfloat162_rn(c, d)) << 32);
}

// ---------------------------------------------------------------------------
// Split-bf16 GEMM via mma.sync: UV[N,256] = x[N,128] @ Wcat[128,256]
// 3 accumulating passes: Ah*Bh + Al*Bh + Ah*Bl  (residual ~2^-18)
// Persistent CTAs; warp tile 64x64 (2x4 warps); per k-step 8 ldmatrix + 32 mma.
// ---------------------------------------------------------------------------
__global__ void __launch_bounds__(256, 1) gemm_mma_kernel(
    const float* __restrict__ x, const float* __restrict__ W1, int N)
{
    extern __shared__ char smem[];
    const u32 sb = smem_u32(smem);
    const int tid = threadIdx.x, wid = tid >> 5, lane = tid & 31;

    // ---- B setup (once per CTA): B[n][k] = Wcat[k][n], hi/lo bf16 ----
    // Thread handles n = tid, 4 k at a time: coalesced LDG (lanes -> consecutive n).
    {
        const int n  = tid;                       // 0..255
        const int nc = n & 127;                   // W1 column
        const int r0 = (n < 128) ? 0 : 128;       // W1 row block
        char* bh = smem + SM_BHI + n * (KP * 2);
        char* bl = smem + SM_BLO + n * (KP * 2);
#pragma unroll 4
        for (int k4 = 0; k4 < 32; ++k4) {
            float v0 = W1[(size_t)(r0 + k4 * 4 + 0) * NODE_DIM + nc];
            float v1 = W1[(size_t)(r0 + k4 * 4 + 1) * NODE_DIM + nc];
            float v2 = W1[(size_t)(r0 + k4 * 4 + 2) * NODE_DIM + nc];
            float v3 = W1[(size_t)(r0 + k4 * 4 + 3) * NODE_DIM + nc];
            float h0 = __bfloat162float(__float2bfloat16(v0));
            float h1 = __bfloat162float(__float2bfloat16(v1));
            float h2 = __bfloat162float(__float2bfloat16(v2));
            float h3 = __bfloat162float(__float2bfloat16(v3));
            *(u64*)(bh + k4 * 8) = hi4(v0, v1, v2, v3);
            *(u64*)(bl + k4 * 8) = hi4(v0 - h0, v1 - h1, v2 - h2, v3 - h3);
        }
    }

    // Per-warp/lane fragment geometry
    const int m0 = (wid & 1) * 64;                 // warp M offset in tile
    const int n0 = (wid >> 1) * 64;                // warp N offset
    const u32 aOffLane = (u32)(((m0 + (lane & 15)) * KP + ((lane >> 4) & 1) * 8) * 2);
    const u32 bOffLane = (u32)(((n0 + ((lane & 16) ? 8 : 0) + (lane & 7)) * KP
                                + ((lane >> 3) & 1) * 8) * 2);
    const u32 aPass[3] = {sb + SM_AHI, sb + SM_ALO, sb + SM_AHI};
    const u32 bPass[3] = {sb + SM_BHI, sb + SM_BHI, sb + SM_BLO};

    const int tiles = (N + 127) >> 7;

    for (int t = blockIdx.x; t < tiles; t += (int)gridDim.x) {
        const int row0 = t * 128;
        __syncthreads();   // previous tile's mma done before overwriting sA

        // ---- A tile: x[row0..+127, :] f32 -> hi/lo bf16 ----
#pragma unroll 4
        for (int it = 0; it < 16; ++it) {
            int idx = it * 256 + tid;
            int r = idx >> 5, c4 = idx & 31;
            int gr = row0 + r;
            float4 xv = make_float4(0.f, 0.f, 0.f, 0.f);
            if (gr < N) xv = *(const float4*)&x[(size_t)gr * NODE_DIM + c4 * 4];
            float hx = __bfloat162float(__float2bfloat16(xv.x));
            float hy = __bfloat162float(__float2bfloat16(xv.y));
            float hz = __bfloat162float(__float2bfloat16(xv.z));
            float hw = __bfloat162float(__float2bfloat16(xv.w));
            u32 off = (u32)(r * (KP * 2) + c4 * 8);
            *(u64*)(smem + SM_AHI + off) = hi4(xv.x, xv.y, xv.z, xv.w);
            *(u64*)(smem + SM_ALO + off) = hi4(xv.x - hx, xv.y - hy, xv.z - hz, xv.w - hw);
        }
        __syncthreads();

        // ---- 3 passes x 8 k-steps of m16n8k16 ----
        float acc[4][8][4];
#pragma unroll
        for (int i = 0; i < 4; ++i)
#pragma unroll
            for (int j = 0; j < 8; ++j)
#pragma unroll
                for (int q = 0; q < 4; ++q) acc[i][j][q] = 0.0f;

#pragma unroll
        for (int p = 0; p < 3; ++p) {
            const u32 aB = aPass[p] + aOffLane;
            const u32 bB = bPass[p] + bOffLane;
#pragma unroll
            for (int ks = 0; ks < 8; ++ks) {
                const u32 ko = (u32)(ks * 32);          // 16 cols * 2 B
                u32 a[4][4];
#pragma unroll
                for (int i = 0; i < 4; ++i)
                    LDSM_X4(a[i][0], a[i][1], a[i][2], a[i][3],
                            aB + ko + (u32)(i * 16 * KP * 2));
                u32 b[8][2];
#pragma unroll
                for (int jj = 0; jj < 4; ++jj)
                    LDSM_X4(b[2 * jj][0], b[2 * jj][1], b[2 * jj + 1][0], b[2 * jj + 1][1],
                            bB + ko + (u32)(jj * 16 * KP * 2));
#pragma unroll
                for (int i = 0; i < 4; ++i)
#pragma unroll
                    for (int j = 0; j < 8; ++j)
                        MMA16816(acc[i][j], a[i], b[j]);
            }
        }

        // ---- Epilogue: acc -> g_UV ----
        const int rA = row0 + m0 + (lane >> 2);
        const int cA = n0 + 2 * (lane & 3);
#pragma unroll
        for (int i = 0; i < 4; ++i) {
            int r0i = rA + 16 * i;
#pragma unroll
            for (int j = 0; j < 8; ++j) {
                int c = cA + 8 * j;
                if (r0i < N)
                    *(float2*)&g_UV[(size_t)r0i * 256 + c] =
                        make_float2(acc[i][j][0], acc[i][j][1]);
                if (r0i + 8 < N)
                    *(float2*)&g_UV[(size_t)(r0i + 8) * 256 + c] =
                        make_float2(acc[i][j][2], acc[i][j][3]);
            }
        }
    }
}

// ---------------------------------------------------------------------------
// Edge pass: one warp per edge, inline dtype detection, 32-bit UV indexing.
//   h = relu(u[src] + v[dst] + b1);  out = sigmoid(h . W2 + b2)
// ---------------------------------------------------------------------------
__global__ void __launch_bounds__(256) edge_kernel(
    const void* __restrict__ ei_raw,
    const float* __restrict__ b1,
    const float* __restrict__ W2,
    const float* __restrict__ b2,
    float* __restrict__ out, int E, int N)
{
    int warp = (int)((blockIdx.x * blockDim.x + threadIdx.x) >> 5);
    int lane = threadIdx.x & 31;

    const long long* p64 = (const long long*)ei_raw;
    long long probe = __ldg(&p64[lane & 15]);
    bool ok = (probe >= 0 && probe < (long long)N);
    bool is64 = (__ballot_sync(0xffffffffu, ok) == 0xffffffffu);

    if (warp >= E) return;

    int s, d;
    if (is64) {
        s = (int)__ldg(&p64[warp]);
        d = (int)__ldg(&p64[(size_t)E + warp]);
    } else {
        const int* ei = (const int*)ei_raw;
        s = __ldg(&ei[warp]);
        d = __ldg(&ei[(size_t)E + warp]);
    }
    s = min(max(s, 0), N - 1);
    d = min(max(d, 0), N - 1);

    unsigned ub = (unsigned)s * 256u + (unsigned)(lane * 4);
    unsigned vb = (unsigned)d * 256u + 128u + (unsigned)(lane * 4);
    float4 u = *(const float4*)&g_UV[ub];
    float4 v = *(const float4*)&g_UV[vb];
    float4 bb = __ldg((const float4*)b1 + lane);
    float4 w  = __ldg((const float4*)W2 + lane);

    float h0 = fmaxf(u.x + v.x + bb.x, 0.0f);
    float h1 = fmaxf(u.y + v.y + bb.y, 0.0f);
    float h2 = fmaxf(u.z + v.z + bb.z, 0.0f);
    float h3 = fmaxf(u.w + v.w + bb.w, 0.0f);

    float p = fmaf(h0, w.x, fmaf(h1, w.y, fmaf(h2, w.z, h3 * w.w)));
#pragma unroll
    for (int off = 16; off > 0; off >>= 1)
        p += __shfl_xor_sync(0xffffffffu, p, off);

    if (lane == 0) {
        float z = p + __ldg(b2);
        out[warp] = 1.0f / (1.0f + expf(-z));
    }
}

// ---------------------------------------------------------------------------
extern "C" void kernel_launch(void* const* d_in, const int* in_sizes, int n_in,
                              void* d_out, int out_size)
{
    const float* x   = (const float*)d_in[0];
    const void*  ei  = d_in[1];
    const float* W1  = (const float*)d_in[2];
    const float* b1  = (const float*)d_in[3];
    const float* W2  = (const float*)d_in[4];
    const float* b2  = (const float*)d_in[5];
    float* out = (float*)d_out;

    int N = in_sizes[0] / NODE_DIM;   // 100000
    int E = in_sizes[1] / 2;          // 600000

    static int smem_set = 0;
    if (!smem_set) {
        cudaFuncSetAttribute(gemm_mma_kernel,
                             cudaFuncAttributeMaxDynamicSharedMemorySize, SM_TOTAL);
        smem_set = 1;
    }

    gemm_mma_kernel<<<148, 256, SM_TOTAL>>>(x, W1, N);

    long long total_threads = (long long)E * 32;
    int blocks = (int)((total_threads + 255) / 256);
    edge_kernel<<<blocks, 256>>>(ei, b1, W2, b2, out, E, N);
}

// round 9
// speedup vs baseline: 1.7845x; 1.2938x over previous
#include <cuda_runtime.h>
#include <cuda_bf16.h>
#include <cuda_fp16.h>
#include <math.h>
#include <string.h>

#define NODE_DIM 128
#define MAX_NODES 100000

typedef unsigned long long u64;
typedef unsigned int u32;

// Scratch: per-node UV[n] = [u[n]+b1 (128) | v[n] (128)] in fp16 (51.2 MB -> L2-resident)
__device__ __align__(16) __half g_UVh[(size_t)MAX_NODES * 256];

// ---------------------------------------------------------------------------
// SMEM layout for GEMM (dynamic, bytes). Rows padded to 136 bf16 (272 B).
// ---------------------------------------------------------------------------
#define KP 136
#define SM_AHI 0
#define SM_ALO 34816
#define SM_BHI 69632
#define SM_BLO 139264
#define SM_TOTAL 208896

#define LDSM_X4(r0, r1, r2, r3, addr) \
    asm volatile("ldmatrix.sync.aligned.m8n8.x4.shared.b16 {%0,%1,%2,%3}, [%4];" \
                 : "=r"(r0), "=r"(r1), "=r"(r2), "=r"(r3) : "r"(addr))

#define MMA16816(c, a, b) \
    asm volatile("mma.sync.aligned.m16n8k16.row.col.f32.bf16.bf16.f32 " \
                 "{%0,%1,%2,%3}, {%4,%5,%6,%7}, {%8,%9}, {%0,%1,%2,%3};" \
                 : "+f"((c)[0]), "+f"((c)[1]), "+f"((c)[2]), "+f"((c)[3]) \
                 : "r"((a)[0]), "r"((a)[1]), "r"((a)[2]), "r"((a)[3]), \
                   "r"((b)[0]), "r"((b)[1]))

__device__ __forceinline__ u32 smem_u32(const void* p) {
    u32 a;
    asm("{ .reg .u64 t; cvta.to.shared.u64 t, %1; cvt.u32.u64 %0, t; }" : "=r"(a) : "l"(p));
    return a;
}
__device__ __forceinline__ u32 bf2_u32(__nv_bfloat162 v) {
    u32 u; memcpy(&u, &v, 4); return u;
}
__device__ __forceinline__ u64 hi4(float a, float b, float c, float d) {
    return (u64)bf2_u32(__floats2bfloat162_rn(a, b))
         | ((u64)bf2_u32(__floats2bfloat162_rn(c, d)) << 32);
}

// ---------------------------------------------------------------------------
// Split-bf16 GEMM via mma.sync: UV[N,256] = x[N,128] @ Wcat[128,256]
// 3 accumulating passes: Ah*Bh + Al*Bh + Ah*Bl. Epilogue: +b1 (u half), fp16.
// ---------------------------------------------------------------------------
__global__ void __launch_bounds__(256, 1) gemm_mma_kernel(
    const float* __restrict__ x, const float* __restrict__ W1,
    const float* __restrict__ b1, int N)
{
    extern __shared__ char smem[];
    const u32 sb = smem_u32(smem);
    const int tid = threadIdx.x, wid = tid >> 5, lane = tid & 31;

    // ---- B setup (once per CTA): B[n][k] = Wcat[k][n], hi/lo bf16 ----
    {
        const int n  = tid;
        const int nc = n & 127;
        const int r0 = (n < 128) ? 0 : 128;
        char* bh = smem + SM_BHI + n * (KP * 2);
        char* bl = smem + SM_BLO + n * (KP * 2);
#pragma unroll 4
        for (int k4 = 0; k4 < 32; ++k4) {
            float v0 = W1[(size_t)(r0 + k4 * 4 + 0) * NODE_DIM + nc];
            float v1 = W1[(size_t)(r0 + k4 * 4 + 1) * NODE_DIM + nc];
            float v2 = W1[(size_t)(r0 + k4 * 4 + 2) * NODE_DIM + nc];
            float v3 = W1[(size_t)(r0 + k4 * 4 + 3) * NODE_DIM + nc];
            float h0 = __bfloat162float(__float2bfloat16(v0));
            float h1 = __bfloat162float(__float2bfloat16(v1));
            float h2 = __bfloat162float(__float2bfloat16(v2));
            float h3 = __bfloat162float(__float2bfloat16(v3));
            *(u64*)(bh + k4 * 8) = hi4(v0, v1, v2, v3);
            *(u64*)(bl + k4 * 8) = hi4(v0 - h0, v1 - h1, v2 - h2, v3 - h3);
        }
    }

    const int m0 = (wid & 1) * 64;
    const int n0 = (wid >> 1) * 64;
    const u32 aOffLane = (u32)(((m0 + (lane & 15)) * KP + ((lane >> 4) & 1) * 8) * 2);
    const u32 bOffLane = (u32)(((n0 + ((lane & 16) ? 8 : 0) + (lane & 7)) * KP
                                + ((lane >> 3) & 1) * 8) * 2);
    const u32 aPass[3] = {sb + SM_AHI, sb + SM_ALO, sb + SM_AHI};
    const u32 bPass[3] = {sb + SM_BHI, sb + SM_BHI, sb + SM_BLO};

    // Preload b1 pairs for this warp's columns (uniform per warp: only n0<128 uses them)
    const int cA = n0 + 2 * (lane & 3);
    float badd[8][2];
#pragma unroll
    for (int j = 0; j < 8; ++j) {
        int c = cA + 8 * j;
        if (c < 128) {
            float2 bv = __ldg((const float2*)&b1[c]);
            badd[j][0] = bv.x; badd[j][1] = bv.y;
        } else {
            badd[j][0] = 0.f; badd[j][1] = 0.f;
        }
    }

    const int tiles = (N + 127) >> 7;

    for (int t = blockIdx.x; t < tiles; t += (int)gridDim.x) {
        const int row0 = t * 128;
        __syncthreads();

        // ---- A tile: x[row0..+127, :] f32 -> hi/lo bf16 ----
#pragma unroll 4
        for (int it = 0; it < 16; ++it) {
            int idx = it * 256 + tid;
            int r = idx >> 5, c4 = idx & 31;
            int gr = row0 + r;
            float4 xv = make_float4(0.f, 0.f, 0.f, 0.f);
            if (gr < N) xv = *(const float4*)&x[(size_t)gr * NODE_DIM + c4 * 4];
            float hx = __bfloat162float(__float2bfloat16(xv.x));
            float hy = __bfloat162float(__float2bfloat16(xv.y));
            float hz = __bfloat162float(__float2bfloat16(xv.z));
            float hw = __bfloat162float(__float2bfloat16(xv.w));
            u32 off = (u32)(r * (KP * 2) + c4 * 8);
            *(u64*)(smem + SM_AHI + off) = hi4(xv.x, xv.y, xv.z, xv.w);
            *(u64*)(smem + SM_ALO + off) = hi4(xv.x - hx, xv.y - hy, xv.z - hz, xv.w - hw);
        }
        __syncthreads();

        // ---- 3 passes x 8 k-steps of m16n8k16 ----
        float acc[4][8][4];
#pragma unroll
        for (int i = 0; i < 4; ++i)
#pragma unroll
            for (int j = 0; j < 8; ++j)
#pragma unroll
                for (int q = 0; q < 4; ++q) acc[i][j][q] = 0.0f;

#pragma unroll
        for (int p = 0; p < 3; ++p) {
            const u32 aB = aPass[p] + aOffLane;
            const u32 bB = bPass[p] + bOffLane;
#pragma unroll
            for (int ks = 0; ks < 8; ++ks) {
                const u32 ko = (u32)(ks * 32);
                u32 a[4][4];
#pragma unroll
                for (int i = 0; i < 4; ++i)
                    LDSM_X4(a[i][0], a[i][1], a[i][2], a[i][3],
                            aB + ko + (u32)(i * 16 * KP * 2));
                u32 b[8][2];
#pragma unroll
                for (int jj = 0; jj < 4; ++jj)
                    LDSM_X4(b[2 * jj][0], b[2 * jj][1], b[2 * jj + 1][0], b[2 * jj + 1][1],
                            bB + ko + (u32)(jj * 16 * KP * 2));
#pragma unroll
                for (int i = 0; i < 4; ++i)
#pragma unroll
                    for (int j = 0; j < 8; ++j)
                        MMA16816(acc[i][j], a[i], b[j]);
            }
        }

        // ---- Epilogue: (+b1 on u half), fp32 -> fp16, store ----
        const int rA = row0 + m0 + (lane >> 2);
#pragma unroll
        for (int i = 0; i < 4; ++i) {
            int r0i = rA + 16 * i;
#pragma unroll
            for (int j = 0; j < 8; ++j) {
                int c = cA + 8 * j;
                if (r0i < N)
                    *(__half2*)&g_UVh[(size_t)r0i * 256 + c] =
                        __floats2half2_rn(acc[i][j][0] + badd[j][0],
                                          acc[i][j][1] + badd[j][1]);
                if (r0i + 8 < N)
                    *(__half2*)&g_UVh[(size_t)(r0i + 8) * 256 + c] =
                        __floats2half2_rn(acc[i][j][2] + badd[j][0],
                                          acc[i][j][3] + badd[j][1]);
            }
        }
    }
}

// ---------------------------------------------------------------------------
// Edge pass: 2 edges per warp (16 lanes each, 8 channels/lane).
//   h = relu(u'[src] + v[dst]);  out = sigmoid(h . W2 + b2)   (b1 folded in u')
// Outputs staged in smem -> one coalesced 64B store per block (16 edges/block).
// ---------------------------------------------------------------------------
__global__ void __launch_bounds__(256) edge_kernel(
    const void* __restrict__ ei_raw,
    const float* __restrict__ W2,
    const float* __restrict__ b2,
    float* __restrict__ out, int E, int N)
{
    __shared__ float s_p[16];
    const int tid  = threadIdx.x;
    const int wid  = tid >> 5;
    const int lane = tid & 31;
    const int grp  = lane >> 4;     // 0/1: which edge in the warp
    const int gl   = lane & 15;     // lane within group -> channels gl*8..+7

    const long long* p64 = (const long long*)ei_raw;
    long long probe = __ldg(&p64[lane & 15]);
    bool okp = (probe >= 0 && probe < (long long)N);
    bool is64 = (__ballot_sync(0xffffffffu, okp) == 0xffffffffu);

    const long long e0 = (long long)blockIdx.x * 16;
    const int e = (int)(e0 + wid * 2 + grp);

    float p = 0.0f;
    if (e < E) {
        int s, d;
        if (is64) {
            s = (int)__ldg(&p64[e]);
            d = (int)__ldg(&p64[(size_t)E + e]);
        } else {
            const int* ei = (const int*)ei_raw;
            s = __ldg(&ei[e]);
            d = __ldg(&ei[(size_t)E + e]);
        }
        s = min(max(s, 0), N - 1);
        d = min(max(d, 0), N - 1);

        // 8 channels per lane: 16B of fp16 per side
        const uint4 uu = *(const uint4*)&g_UVh[(size_t)s * 256 + gl * 8];
        const uint4 vv = *(const uint4*)&g_UVh[(size_t)d * 256 + 128 + gl * 8];
        const float4 w0 = __ldg((const float4*)W2 + gl * 2);
        const float4 w1 = __ldg((const float4*)W2 + gl * 2 + 1);

        float2 ua = __half22float2(*(const __half2*)&uu.x);
        float2 ub = __half22float2(*(const __half2*)&uu.y);
        float2 uc = __half22float2(*(const __half2*)&uu.z);
        float2 ud = __half22float2(*(const __half2*)&uu.w);
        float2 va = __half22float2(*(const __half2*)&vv.x);
        float2 vb = __half22float2(*(const __half2*)&vv.y);
        float2 vc = __half22float2(*(const __half2*)&vv.z);
        float2 vd = __half22float2(*(const __half2*)&vv.w);

        float h0 = fmaxf(ua.x + va.x, 0.f), h1 = fmaxf(ua.y + va.y, 0.f);
        float h2 = fmaxf(ub.x + vb.x, 0.f), h3 = fmaxf(ub.y + vb.y, 0.f);
        float h4 = fmaxf(uc.x + vc.x, 0.f), h5 = fmaxf(uc.y + vc.y, 0.f);
        float h6 = fmaxf(ud.x + vd.x, 0.f), h7 = fmaxf(ud.y + vd.y, 0.f);

        p = fmaf(h0, w0.x, fmaf(h1, w0.y, fmaf(h2, w0.z, h3 * w0.w)));
        p = fmaf(h4, w1.x, fmaf(h5, w1.y, fmaf(h6, w1.z, fmaf(h7, w1.w, p))));
    }

    // reduce within 16-lane group
#pragma unroll
    for (int off = 8; off > 0; off >>= 1)
        p += __shfl_xor_sync(0xffffffffu, p, off);

    if (gl == 0) s_p[wid * 2 + grp] = p;
    __syncthreads();

    if (tid < 16) {
        long long eo = e0 + tid;
        if (eo < E) {
            float z = s_p[tid] + __ldg(b2);
            out[eo] = 1.0f / (1.0f + expf(-z));
        }
    }
}

// ---------------------------------------------------------------------------
extern "C" void kernel_launch(void* const* d_in, const int* in_sizes, int n_in,
                              void* d_out, int out_size)
{
    const float* x   = (const float*)d_in[0];
    const void*  ei  = d_in[1];
    const float* W1  = (const float*)d_in[2];
    const float* b1  = (const float*)d_in[3];
    const float* W2  = (const float*)d_in[4];
    const float* b2  = (const float*)d_in[5];
    float* out = (float*)d_out;

    int N = in_sizes[0] / NODE_DIM;   // 100000
    int E = in_sizes[1] / 2;          // 600000

    static int smem_set = 0;
    if (!smem_set) {
        cudaFuncSetAttribute(gemm_mma_kernel,
                             cudaFuncAttributeMaxDynamicSharedMemorySize, SM_TOTAL);
        smem_set = 1;
    }

    gemm_mma_kernel<<<148, 256, SM_TOTAL>>>(x, W1, b1, N);

    int blocks = (E + 15) / 16;
    edge_kernel<<<blocks, 256>>>(ei, W2, b2, out, E, N);
}

// round 10
// speedup vs baseline: 2.0580x; 1.1533x over previous
#include <cuda_runtime.h>
#include <cuda_bf16.h>
#include <cuda_fp16.h>
#include <math.h>
#include <string.h>

#define NODE_DIM 128
#define MAX_NODES 100000

typedef unsigned long long u64;
typedef unsigned int u32;

// Scratch: per-node UV[n] = [u[n]+b1 (128) | v[n] (128)] in fp16, 51.2 MB.
// Columns are PERMUTED within each 64-block: p = 16a + 2j + q for original
// c = 2a + 8j + q (a=0..3, j=0..7, q=0..1). Edge kernel compensates via W2p.
__device__ __align__(16) __half g_UVh[(size_t)MAX_NODES * 256];

// ---------------------------------------------------------------------------
// SMEM layout for GEMM (dynamic, bytes). Rows padded to 136 bf16 (272 B).
// ---------------------------------------------------------------------------
#define KP 136
#define SM_AHI 0
#define SM_ALO 34816
#define SM_BHI 69632
#define SM_BLO 139264
#define SM_TOTAL 208896

#define LDSM_X4(r0, r1, r2, r3, addr) \
    asm volatile("ldmatrix.sync.aligned.m8n8.x4.shared.b16 {%0,%1,%2,%3}, [%4];" \
                 : "=r"(r0), "=r"(r1), "=r"(r2), "=r"(r3) : "r"(addr))

#define MMA16816(c, a, b) \
    asm volatile("mma.sync.aligned.m16n8k16.row.col.f32.bf16.bf16.f32 " \
                 "{%0,%1,%2,%3}, {%4,%5,%6,%7}, {%8,%9}, {%0,%1,%2,%3};" \
                 : "+f"((c)[0]), "+f"((c)[1]), "+f"((c)[2]), "+f"((c)[3]) \
                 : "r"((a)[0]), "r"((a)[1]), "r"((a)[2]), "r"((a)[3]), \
                   "r"((b)[0]), "r"((b)[1]))

__device__ __forceinline__ u32 smem_u32(const void* p) {
    u32 a;
    asm("{ .reg .u64 t; cvta.to.shared.u64 t, %1; cvt.u32.u64 %0, t; }" : "=r"(a) : "l"(p));
    return a;
}
__device__ __forceinline__ u32 bf2_u32(__nv_bfloat162 v) {
    u32 u; memcpy(&u, &v, 4); return u;
}
__device__ __forceinline__ u64 hi4(float a, float b, float c, float d) {
    return (u64)bf2_u32(__floats2bfloat162_rn(a, b))
         | ((u64)bf2_u32(__floats2bfloat162_rn(c, d)) << 32);
}
__device__ __forceinline__ u32 h2_u32(float a, float b) {
    __half2 h = __floats2half2_rn(a, b);
    u32 u; memcpy(&u, &h, 4); return u;
}

// ---------------------------------------------------------------------------
// Split-bf16 GEMM via mma.sync: UV[N,256] = x[N,128] @ Wcat[128,256]
// 3 accumulating passes: Ah*Bh + Al*Bh + Ah*Bl. Epilogue: +b1, fp16,
// permuted columns -> contiguous 32B per thread per row (STG.128).
// ---------------------------------------------------------------------------
__global__ void __launch_bounds__(256, 1) gemm_mma_kernel(
    const float* __restrict__ x, const float* __restrict__ W1,
    const float* __restrict__ b1, int N)
{
    extern __shared__ char smem[];
    const u32 sb = smem_u32(smem);
    const int tid = threadIdx.x, wid = tid >> 5, lane = tid & 31;

    // ---- B setup (once per CTA): B[n][k] = Wcat[k][n], hi/lo bf16 ----
    {
        const int n  = tid;
        const int nc = n & 127;
        const int r0 = (n < 128) ? 0 : 128;
        char* bh = smem + SM_BHI + n * (KP * 2);
        char* bl = smem + SM_BLO + n * (KP * 2);
#pragma unroll 4
        for (int k4 = 0; k4 < 32; ++k4) {
            float v0 = W1[(size_t)(r0 + k4 * 4 + 0) * NODE_DIM + nc];
            float v1 = W1[(size_t)(r0 + k4 * 4 + 1) * NODE_DIM + nc];
            float v2 = W1[(size_t)(r0 + k4 * 4 + 2) * NODE_DIM + nc];
            float v3 = W1[(size_t)(r0 + k4 * 4 + 3) * NODE_DIM + nc];
            float h0 = __bfloat162float(__float2bfloat16(v0));
            float h1 = __bfloat162float(__float2bfloat16(v1));
            float h2 = __bfloat162float(__float2bfloat16(v2));
            float h3 = __bfloat162float(__float2bfloat16(v3));
            *(u64*)(bh + k4 * 8) = hi4(v0, v1, v2, v3);
            *(u64*)(bl + k4 * 8) = hi4(v0 - h0, v1 - h1, v2 - h2, v3 - h3);
        }
    }

    const int m0 = (wid & 1) * 64;
    const int n0 = (wid >> 1) * 64;
    const u32 aOffLane = (u32)(((m0 + (lane & 15)) * KP + ((lane >> 4) & 1) * 8) * 2);
    const u32 bOffLane = (u32)(((n0 + ((lane & 16) ? 8 : 0) + (lane & 7)) * KP
                                + ((lane >> 3) & 1) * 8) * 2);
    const u32 aPass[3] = {sb + SM_AHI, sb + SM_ALO, sb + SM_AHI};
    const u32 bPass[3] = {sb + SM_BHI, sb + SM_BHI, sb + SM_BLO};

    // b1 pairs for this thread's original columns c = n0 + 2a + 8j + q
    const int aIdx = lane & 3;
    const int cA = n0 + 2 * aIdx;
    float badd[8][2];
#pragma unroll
    for (int j = 0; j < 8; ++j) {
        int c = cA + 8 * j;
        if (c < 128) {
            float2 bv = __ldg((const float2*)&b1[c]);
            badd[j][0] = bv.x; badd[j][1] = bv.y;
        } else {
            badd[j][0] = 0.f; badd[j][1] = 0.f;
        }
    }

    const int tiles = (N + 127) >> 7;

    for (int t = blockIdx.x; t < tiles; t += (int)gridDim.x) {
        const int row0 = t * 128;
        __syncthreads();

        // ---- A tile: x[row0..+127, :] f32 -> hi/lo bf16 ----
#pragma unroll 4
        for (int it = 0; it < 16; ++it) {
            int idx = it * 256 + tid;
            int r = idx >> 5, c4 = idx & 31;
            int gr = row0 + r;
            float4 xv = make_float4(0.f, 0.f, 0.f, 0.f);
            if (gr < N) xv = *(const float4*)&x[(size_t)gr * NODE_DIM + c4 * 4];
            float hx = __bfloat162float(__float2bfloat16(xv.x));
            float hy = __bfloat162float(__float2bfloat16(xv.y));
            float hz = __bfloat162float(__float2bfloat16(xv.z));
            float hw = __bfloat162float(__float2bfloat16(xv.w));
            u32 off = (u32)(r * (KP * 2) + c4 * 8);
            *(u64*)(smem + SM_AHI + off) = hi4(xv.x, xv.y, xv.z, xv.w);
            *(u64*)(smem + SM_ALO + off) = hi4(xv.x - hx, xv.y - hy, xv.z - hz, xv.w - hw);
        }
        __syncthreads();

        // ---- 3 passes x 8 k-steps of m16n8k16 ----
        float acc[4][8][4];
#pragma unroll
        for (int i = 0; i < 4; ++i)
#pragma unroll
            for (int j = 0; j < 8; ++j)
#pragma unroll
                for (int q = 0; q < 4; ++q) acc[i][j][q] = 0.0f;

#pragma unroll
        for (int p = 0; p < 3; ++p) {
            const u32 aB = aPass[p] + aOffLane;
            const u32 bB = bPass[p] + bOffLane;
#pragma unroll
            for (int ks = 0; ks < 8; ++ks) {
                const u32 ko = (u32)(ks * 32);
                u32 a[4][4];
#pragma unroll
                for (int i = 0; i < 4; ++i)
                    LDSM_X4(a[i][0], a[i][1], a[i][2], a[i][3],
                            aB + ko + (u32)(i * 16 * KP * 2));
                u32 b[8][2];
#pragma unroll
                for (int jj = 0; jj < 4; ++jj)
                    LDSM_X4(b[2 * jj][0], b[2 * jj][1], b[2 * jj + 1][0], b[2 * jj + 1][1],
                            bB + ko + (u32)(jj * 16 * KP * 2));
#pragma unroll
                for (int i = 0; i < 4; ++i)
#pragma unroll
                    for (int j = 0; j < 8; ++j)
                        MMA16816(acc[i][j], a[i], b[j]);
            }
        }

        // ---- Epilogue: +b1, fp16, permuted -> 2x STG.128 per row ----
        const int rA = row0 + m0 + (lane >> 2);
        const u32 colBase = (u32)(n0 + 16 * aIdx);
#pragma unroll
        for (int i = 0; i < 4; ++i) {
#pragma unroll
            for (int half = 0; half < 2; ++half) {
                int r = rA + 16 * i + 8 * half;
                if (r < N) {
                    u32 w[8];
#pragma unroll
                    for (int j = 0; j < 8; ++j)
                        w[j] = h2_u32(acc[i][j][2 * half + 0] + badd[j][0],
                                      acc[i][j][2 * half + 1] + badd[j][1]);
                    __half* dst = &g_UVh[(size_t)r * 256 + colBase];
                    *(uint4*)dst = make_uint4(w[0], w[1], w[2], w[3]);
                    *(uint4*)(dst + 8) = make_uint4(w[4], w[5], w[6], w[7]);
                }
            }
        }
    }
}

// ---------------------------------------------------------------------------
// Edge pass: 2 edges per 16-lane group (4 per warp, 32 per block).
//   h_p = relu(u'[s]_p + v[d]_p);  out = sigmoid(sum_p h_p * W2p[p] + b2)
// W2p[p] = W2[c(p)] undoes the GEMM's column permutation.
// ---------------------------------------------------------------------------
__global__ void __launch_bounds__(256) edge_kernel(
    const void* __restrict__ ei_raw,
    const float* __restrict__ W2,
    const float* __restrict__ b2,
    float* __restrict__ out, int E, int N)
{
    __shared__ float s_p[32];
    __shared__ float s_w2p[128];

    const int tid  = threadIdx.x;
    const int wid  = tid >> 5;
    const int lane = tid & 31;
    const int grp  = lane >> 4;
    const int gl   = lane & 15;

    // Permuted W2: p -> c = blk*64 + 2a + 8j + q, a=p[5:4], j=p[3:1], q=p[0]
    if (tid < 128) {
        int blk = tid >> 6, r = tid & 63;
        int c = blk * 64 + 2 * (r >> 4) + 8 * ((r >> 1) & 7) + (r & 1);
        s_w2p[tid] = __ldg(&W2[c]);
    }

    const long long* p64 = (const long long*)ei_raw;
    long long probe = __ldg(&p64[lane & 15]);
    bool okp = (probe >= 0 && probe < (long long)N);
    bool is64 = (__ballot_sync(0xffffffffu, okp) == 0xffffffffu);

    __syncthreads();

    const long long e0 = (long long)blockIdx.x * 32;
    const int gidx = wid * 2 + grp;          // 0..15
    const int ea = (int)(e0 + gidx * 2);
    const int eb = ea + 1;

    const float4 w0 = *(const float4*)&s_w2p[gl * 8];
    const float4 w1 = *(const float4*)&s_w2p[gl * 8 + 4];

    float pa = 0.0f, pb = 0.0f;

    int sa = 0, da = 0, sc = 0, dc = 0;
    bool va_ = (ea < E), vb_ = (eb < E);
    if (va_) {
        if (is64) {
            sa = (int)__ldg(&p64[ea]);
            da = (int)__ldg(&p64[(size_t)E + ea]);
        } else {
            const int* ei = (const int*)ei_raw;
            sa = __ldg(&ei[ea]);
            da = __ldg(&ei[(size_t)E + ea]);
        }
        sa = min(max(sa, 0), N - 1); da = min(max(da, 0), N - 1);
    }
    if (vb_) {
        if (is64) {
            sc = (int)__ldg(&p64[eb]);
            dc = (int)__ldg(&p64[(size_t)E + eb]);
        } else {
            const int* ei = (const int*)ei_raw;
            sc = __ldg(&ei[eb]);
            dc = __ldg(&ei[(size_t)E + eb]);
        }
        sc = min(max(sc, 0), N - 1); dc = min(max(dc, 0), N - 1);
    }

    // 4 independent gathers in flight
    uint4 ua4 = make_uint4(0, 0, 0, 0), va4 = ua4, ub4 = ua4, vb4 = ua4;
    if (va_) {
        ua4 = *(const uint4*)&g_UVh[(size_t)sa * 256 + gl * 8];
        va4 = *(const uint4*)&g_UVh[(size_t)da * 256 + 128 + gl * 8];
    }
    if (vb_) {
        ub4 = *(const uint4*)&g_UVh[(size_t)sc * 256 + gl * 8];
        vb4 = *(const uint4*)&g_UVh[(size_t)dc * 256 + 128 + gl * 8];
    }

    {
        float2 u0 = __half22float2(*(const __half2*)&ua4.x);
        float2 u1 = __half22float2(*(const __half2*)&ua4.y);
        float2 u2 = __half22float2(*(const __half2*)&ua4.z);
        float2 u3 = __half22float2(*(const __half2*)&ua4.w);
        float2 v0 = __half22float2(*(const __half2*)&va4.x);
        float2 v1 = __half22float2(*(const __half2*)&va4.y);
        float2 v2 = __half22float2(*(const __half2*)&va4.z);
        float2 v3 = __half22float2(*(const __half2*)&va4.w);
        float h0 = fmaxf(u0.x + v0.x, 0.f), h1 = fmaxf(u0.y + v0.y, 0.f);
        float h2 = fmaxf(u1.x + v1.x, 0.f), h3 = fmaxf(u1.y + v1.y, 0.f);
        float h4 = fmaxf(u2.x + v2.x, 0.f), h5 = fmaxf(u2.y + v2.y, 0.f);
        float h6 = fmaxf(u3.x + v3.x, 0.f), h7 = fmaxf(u3.y + v3.y, 0.f);
        pa = fmaf(h0, w0.x, fmaf(h1, w0.y, fmaf(h2, w0.z, h3 * w0.w)));
        pa = fmaf(h4, w1.x, fmaf(h5, w1.y, fmaf(h6, w1.z, fmaf(h7, w1.w, pa))));
    }
    {
        float2 u0 = __half22float2(*(const __half2*)&ub4.x);
        float2 u1 = __half22float2(*(const __half2*)&ub4.y);
        float2 u2 = __half22float2(*(const __half2*)&ub4.z);
        float2 u3 = __half22float2(*(const __half2*)&ub4.w);
        float2 v0 = __half22float2(*(const __half2*)&vb4.x);
        float2 v1 = __half22float2(*(const __half2*)&vb4.y);
        float2 v2 = __half22float2(*(const __half2*)&vb4.z);
        float2 v3 = __half22float2(*(const __half2*)&vb4.w);
        float h0 = fmaxf(u0.x + v0.x, 0.f), h1 = fmaxf(u0.y + v0.y, 0.f);
        float h2 = fmaxf(u1.x + v1.x, 0.f), h3 = fmaxf(u1.y + v1.y, 0.f);
        float h4 = fmaxf(u2.x + v2.x, 0.f), h5 = fmaxf(u2.y + v2.y, 0.f);
        float h6 = fmaxf(u3.x + v3.x, 0.f), h7 = fmaxf(u3.y + v3.y, 0.f);
        pb = fmaf(h0, w0.x, fmaf(h1, w0.y, fmaf(h2, w0.z, h3 * w0.w)));
        pb = fmaf(h4, w1.x, fmaf(h5, w1.y, fmaf(h6, w1.z, fmaf(h7, w1.w, pb))));
    }

#pragma unroll
    for (int off = 8; off > 0; off >>= 1) {
        pa += __shfl_xor_sync(0xffffffffu, pa, off);
        pb += __shfl_xor_sync(0xffffffffu, pb, off);
    }

    if (gl == 0) {
        s_p[gidx * 2]     = pa;
        s_p[gidx * 2 + 1] = pb;
    }
    __syncthreads();

    if (tid < 32) {
        long long eo = e0 + tid;
        if (eo < E) {
            float z = s_p[tid] + __ldg(b2);
            out[eo] = 1.0f / (1.0f + expf(-z));
        }
    }
}

// ---------------------------------------------------------------------------
extern "C" void kernel_launch(void* const* d_in, const int* in_sizes, int n_in,
                              void* d_out, int out_size)
{
    const float* x   = (const float*)d_in[0];
    const void*  ei  = d_in[1];
    const float* W1  = (const float*)d_in[2];
    const float* b1  = (const float*)d_in[3];
    const float* W2  = (const float*)d_in[4];
    const float* b2  = (const float*)d_in[5];
    float* out = (float*)d_out;

    int N = in_sizes[0] / NODE_DIM;   // 100000
    int E = in_sizes[1] / 2;          // 600000

    static int smem_set = 0;
    if (!smem_set) {
        cudaFuncSetAttribute(gemm_mma_kernel,
                             cudaFuncAttributeMaxDynamicSharedMemorySize, SM_TOTAL);
        smem_set = 1;
    }

    gemm_mma_kernel<<<148, 256, SM_TOTAL>>>(x, W1, b1, N);

    int blocks = (E + 31) / 32;
    edge_kernel<<<blocks, 256>>>(ei, W2, b2, out, E, N);
}

// round 11
// speedup vs baseline: 2.2729x; 1.1045x over previous
#include <cuda_runtime.h>
#include <cuda_bf16.h>
#include <cuda_fp16.h>
#include <math.h>
#include <string.h>

#define NODE_DIM 128
#define MAX_NODES 100000

typedef unsigned long long u64;
typedef unsigned int u32;

// Scratch: per-node UV[n] = [u[n]+b1 (128) | v[n] (128)] in fp16, 51.2 MB.
// Columns PERMUTED within each 64-block: p = 16a + 2j + q for c = 2a + 8j + q.
__device__ __align__(16) __half g_UVh[(size_t)MAX_NODES * 256];

// ---------------------------------------------------------------------------
// SMEM layout for GEMM (dynamic, bytes). Rows padded to 136 bf16 (272 B).
// ---------------------------------------------------------------------------
#define KP 136
#define SM_AHI 0
#define SM_ALO 34816
#define SM_BHI 69632
#define SM_BLO 139264
#define SM_TOTAL 208896

#define LDSM_X4(r0, r1, r2, r3, addr) \
    asm volatile("ldmatrix.sync.aligned.m8n8.x4.shared.b16 {%0,%1,%2,%3}, [%4];" \
                 : "=r"(r0), "=r"(r1), "=r"(r2), "=r"(r3) : "r"(addr))

#define MMA16816(c, a, b) \
    asm volatile("mma.sync.aligned.m16n8k16.row.col.f32.bf16.bf16.f32 " \
                 "{%0,%1,%2,%3}, {%4,%5,%6,%7}, {%8,%9}, {%0,%1,%2,%3};" \
                 : "+f"((c)[0]), "+f"((c)[1]), "+f"((c)[2]), "+f"((c)[3]) \
                 : "r"((a)[0]), "r"((a)[1]), "r"((a)[2]), "r"((a)[3]), \
                   "r"((b)[0]), "r"((b)[1]))

__device__ __forceinline__ u32 smem_u32(const void* p) {
    u32 a;
    asm("{ .reg .u64 t; cvta.to.shared.u64 t, %1; cvt.u32.u64 %0, t; }" : "=r"(a) : "l"(p));
    return a;
}
__device__ __forceinline__ u32 bf2_u32(__nv_bfloat162 v) {
    u32 u; memcpy(&u, &v, 4); return u;
}
__device__ __forceinline__ u64 hi4(float a, float b, float c, float d) {
    return (u64)bf2_u32(__floats2bfloat162_rn(a, b))
         | ((u64)bf2_u32(__floats2bfloat162_rn(c, d)) << 32);
}
__device__ __forceinline__ u32 h2_u32(float a, float b) {
    __half2 h = __floats2half2_rn(a, b);
    u32 u; memcpy(&u, &h, 4); return u;
}

// ---------------------------------------------------------------------------
// Split-bf16 GEMM via mma.sync: UV[N,256] = x[N,128] @ Wcat[128,256]
// Merged 3-pass k-loop: per k-step load Ah,Al,Bh,Bl frags ONCE (16 LDSM),
// then 96 MMAs: Ah*Bh + Al*Bh + Ah*Bl.
// ---------------------------------------------------------------------------
__global__ void __launch_bounds__(256, 1) gemm_mma_kernel(
    const float* __restrict__ x, const float* __restrict__ W1,
    const float* __restrict__ b1, int N)
{
    extern __shared__ char smem[];
    const u32 sb = smem_u32(smem);
    const int tid = threadIdx.x, wid = tid >> 5, lane = tid & 31;

    // ---- B setup (once per CTA): B[n][k] = Wcat[k][n], hi/lo bf16 ----
    {
        const int n  = tid;
        const int nc = n & 127;
        const int r0 = (n < 128) ? 0 : 128;
        char* bh = smem + SM_BHI + n * (KP * 2);
        char* bl = smem + SM_BLO + n * (KP * 2);
#pragma unroll 4
        for (int k4 = 0; k4 < 32; ++k4) {
            float v0 = W1[(size_t)(r0 + k4 * 4 + 0) * NODE_DIM + nc];
            float v1 = W1[(size_t)(r0 + k4 * 4 + 1) * NODE_DIM + nc];
            float v2 = W1[(size_t)(r0 + k4 * 4 + 2) * NODE_DIM + nc];
            float v3 = W1[(size_t)(r0 + k4 * 4 + 3) * NODE_DIM + nc];
            float h0 = __bfloat162float(__float2bfloat16(v0));
            float h1 = __bfloat162float(__float2bfloat16(v1));
            float h2 = __bfloat162float(__float2bfloat16(v2));
            float h3 = __bfloat162float(__float2bfloat16(v3));
            *(u64*)(bh + k4 * 8) = hi4(v0, v1, v2, v3);
            *(u64*)(bl + k4 * 8) = hi4(v0 - h0, v1 - h1, v2 - h2, v3 - h3);
        }
    }

    const int m0 = (wid & 1) * 64;
    const int n0 = (wid >> 1) * 64;
    const u32 aOffLane = (u32)(((m0 + (lane & 15)) * KP + ((lane >> 4) & 1) * 8) * 2);
    const u32 bOffLane = (u32)(((n0 + ((lane & 16) ? 8 : 0) + (lane & 7)) * KP
                                + ((lane >> 3) & 1) * 8) * 2);
    const u32 aHiB = sb + SM_AHI + aOffLane;
    const u32 aLoB = sb + SM_ALO + aOffLane;
    const u32 bHiB = sb + SM_BHI + bOffLane;
    const u32 bLoB = sb + SM_BLO + bOffLane;

    // b1 pairs for this thread's original columns c = n0 + 2a + 8j + q
    const int aIdx = lane & 3;
    const int cA = n0 + 2 * aIdx;
    float badd[8][2];
#pragma unroll
    for (int j = 0; j < 8; ++j) {
        int c = cA + 8 * j;
        if (c < 128) {
            float2 bv = __ldg((const float2*)&b1[c]);
            badd[j][0] = bv.x; badd[j][1] = bv.y;
        } else {
            badd[j][0] = 0.f; badd[j][1] = 0.f;
        }
    }

    const int tiles = (N + 127) >> 7;

    for (int t = blockIdx.x; t < tiles; t += (int)gridDim.x) {
        const int row0 = t * 128;
        __syncthreads();

        // ---- A tile: x[row0..+127, :] f32 -> hi/lo bf16 ----
#pragma unroll 4
        for (int it = 0; it < 16; ++it) {
            int idx = it * 256 + tid;
            int r = idx >> 5, c4 = idx & 31;
            int gr = row0 + r;
            float4 xv = make_float4(0.f, 0.f, 0.f, 0.f);
            if (gr < N) xv = *(const float4*)&x[(size_t)gr * NODE_DIM + c4 * 4];
            float hx = __bfloat162float(__float2bfloat16(xv.x));
            float hy = __bfloat162float(__float2bfloat16(xv.y));
            float hz = __bfloat162float(__float2bfloat16(xv.z));
            float hw = __bfloat162float(__float2bfloat16(xv.w));
            u32 off = (u32)(r * (KP * 2) + c4 * 8);
            *(u64*)(smem + SM_AHI + off) = hi4(xv.x, xv.y, xv.z, xv.w);
            *(u64*)(smem + SM_ALO + off) = hi4(xv.x - hx, xv.y - hy, xv.z - hz, xv.w - hw);
        }
        __syncthreads();

        // ---- Merged 3-pass mainloop: 8 k-steps, 16 LDSM + 96 MMA each ----
        float acc[4][8][4];
#pragma unroll
        for (int i = 0; i < 4; ++i)
#pragma unroll
            for (int j = 0; j < 8; ++j)
#pragma unroll
                for (int q = 0; q < 4; ++q) acc[i][j][q] = 0.0f;

#pragma unroll
        for (int ks = 0; ks < 8; ++ks) {
            const u32 ko = (u32)(ks * 32);

            u32 ah[4][4], bh[8][2];
#pragma unroll
            for (int i = 0; i < 4; ++i)
                LDSM_X4(ah[i][0], ah[i][1], ah[i][2], ah[i][3],
                        aHiB + ko + (u32)(i * 16 * KP * 2));
#pragma unroll
            for (int jj = 0; jj < 4; ++jj)
                LDSM_X4(bh[2 * jj][0], bh[2 * jj][1], bh[2 * jj + 1][0], bh[2 * jj + 1][1],
                        bHiB + ko + (u32)(jj * 16 * KP * 2));
            // pass 1: Ah * Bh
#pragma unroll
            for (int i = 0; i < 4; ++i)
#pragma unroll
                for (int j = 0; j < 8; ++j)
                    MMA16816(acc[i][j], ah[i], bh[j]);

            // pass 2: Al * Bh
            u32 al[4][4];
#pragma unroll
            for (int i = 0; i < 4; ++i)
                LDSM_X4(al[i][0], al[i][1], al[i][2], al[i][3],
                        aLoB + ko + (u32)(i * 16 * KP * 2));
#pragma unroll
            for (int i = 0; i < 4; ++i)
#pragma unroll
                for (int j = 0; j < 8; ++j)
                    MMA16816(acc[i][j], al[i], bh[j]);

            // pass 3: Ah * Bl
            u32 bl[8][2];
#pragma unroll
            for (int jj = 0; jj < 4; ++jj)
                LDSM_X4(bl[2 * jj][0], bl[2 * jj][1], bl[2 * jj + 1][0], bl[2 * jj + 1][1],
                        bLoB + ko + (u32)(jj * 16 * KP * 2));
#pragma unroll
            for (int i = 0; i < 4; ++i)
#pragma unroll
                for (int j = 0; j < 8; ++j)
                    MMA16816(acc[i][j], ah[i], bl[j]);
        }

        // ---- Epilogue: +b1, fp16, permuted -> 2x STG.128 per row ----
        const int rA = row0 + m0 + (lane >> 2);
        const u32 colBase = (u32)(n0 + 16 * aIdx);
#pragma unroll
        for (int i = 0; i < 4; ++i) {
#pragma unroll
            for (int half = 0; half < 2; ++half) {
                int r = rA + 16 * i + 8 * half;
                if (r < N) {
                    u32 w[8];
#pragma unroll
                    for (int j = 0; j < 8; ++j)
                        w[j] = h2_u32(acc[i][j][2 * half + 0] + badd[j][0],
                                      acc[i][j][2 * half + 1] + badd[j][1]);
                    __half* dst = &g_UVh[(size_t)r * 256 + colBase];
                    *(uint4*)dst = make_uint4(w[0], w[1], w[2], w[3]);
                    *(uint4*)(dst + 8) = make_uint4(w[4], w[5], w[6], w[7]);
                }
            }
        }
    }
}

// ---------------------------------------------------------------------------
// Edge pass: 2 edges per 16-lane group (4 per warp, 32 per block).
//   h_p = relu(u'[s]_p + v[d]_p);  out = sigmoid(sum_p h_p * W2p[p] + b2)
// ---------------------------------------------------------------------------
__global__ void __launch_bounds__(256) edge_kernel(
    const void* __restrict__ ei_raw,
    const float* __restrict__ W2,
    const float* __restrict__ b2,
    float* __restrict__ out, int E, int N)
{
    __shared__ float s_p[32];
    __shared__ float s_w2p[128];

    const int tid  = threadIdx.x;
    const int wid  = tid >> 5;
    const int lane = tid & 31;
    const int grp  = lane >> 4;
    const int gl   = lane & 15;

    if (tid < 128) {
        int blk = tid >> 6, r = tid & 63;
        int c = blk * 64 + 2 * (r >> 4) + 8 * ((r >> 1) & 7) + (r & 1);
        s_w2p[tid] = __ldg(&W2[c]);
    }

    const long long* p64 = (const long long*)ei_raw;
    long long probe = __ldg(&p64[lane & 15]);
    bool okp = (probe >= 0 && probe < (long long)N);
    bool is64 = (__ballot_sync(0xffffffffu, okp) == 0xffffffffu);

    __syncthreads();

    const long long e0 = (long long)blockIdx.x * 32;
    const int gidx = wid * 2 + grp;
    const int ea = (int)(e0 + gidx * 2);
    const int eb = ea + 1;

    const float4 w0 = *(const float4*)&s_w2p[gl * 8];
    const float4 w1 = *(const float4*)&s_w2p[gl * 8 + 4];

    float pa = 0.0f, pb = 0.0f;

    int sa = 0, da = 0, sc = 0, dc = 0;
    bool va_ = (ea < E), vb_ = (eb < E);
    if (va_) {
        if (is64) {
            sa = (int)__ldg(&p64[ea]);
            da = (int)__ldg(&p64[(size_t)E + ea]);
        } else {
            const int* ei = (const int*)ei_raw;
            sa = __ldg(&ei[ea]);
            da = __ldg(&ei[(size_t)E + ea]);
        }
        sa = min(max(sa, 0), N - 1); da = min(max(da, 0), N - 1);
    }
    if (vb_) {
        if (is64) {
            sc = (int)__ldg(&p64[eb]);
            dc = (int)__ldg(&p64[(size_t)E + eb]);
        } else {
            const int* ei = (const int*)ei_raw;
            sc = __ldg(&ei[eb]);
            dc = __ldg(&ei[(size_t)E + eb]);
        }
        sc = min(max(sc, 0), N - 1); dc = min(max(dc, 0), N - 1);
    }

    uint4 ua4 = make_uint4(0, 0, 0, 0), va4 = ua4, ub4 = ua4, vb4 = ua4;
    if (va_) {
        ua4 = *(const uint4*)&g_UVh[(size_t)sa * 256 + gl * 8];
        va4 = *(const uint4*)&g_UVh[(size_t)da * 256 + 128 + gl * 8];
    }
    if (vb_) {
        ub4 = *(const uint4*)&g_UVh[(size_t)sc * 256 + gl * 8];
        vb4 = *(const uint4*)&g_UVh[(size_t)dc * 256 + 128 + gl * 8];
    }

    {
        float2 u0 = __half22float2(*(const __half2*)&ua4.x);
        float2 u1 = __half22float2(*(const __half2*)&ua4.y);
        float2 u2 = __half22float2(*(const __half2*)&ua4.z);
        float2 u3 = __half22float2(*(const __half2*)&ua4.w);
        float2 v0 = __half22float2(*(const __half2*)&va4.x);
        float2 v1 = __half22float2(*(const __half2*)&va4.y);
        float2 v2 = __half22float2(*(const __half2*)&va4.z);
        float2 v3 = __half22float2(*(const __half2*)&va4.w);
        float h0 = fmaxf(u0.x + v0.x, 0.f), h1 = fmaxf(u0.y + v0.y, 0.f);
        float h2 = fmaxf(u1.x + v1.x, 0.f), h3 = fmaxf(u1.y + v1.y, 0.f);
        float h4 = fmaxf(u2.x + v2.x, 0.f), h5 = fmaxf(u2.y + v2.y, 0.f);
        float h6 = fmaxf(u3.x + v3.x, 0.f), h7 = fmaxf(u3.y + v3.y, 0.f);
        pa = fmaf(h0, w0.x, fmaf(h1, w0.y, fmaf(h2, w0.z, h3 * w0.w)));
        pa = fmaf(h4, w1.x, fmaf(h5, w1.y, fmaf(h6, w1.z, fmaf(h7, w1.w, pa))));
    }
    {
        float2 u0 = __half22float2(*(const __half2*)&ub4.x);
        float2 u1 = __half22float2(*(const __half2*)&ub4.y);
        float2 u2 = __half22float2(*(const __half2*)&ub4.z);
        float2 u3 = __half22float2(*(const __half2*)&ub4.w);
        float2 v0 = __half22float2(*(const __half2*)&vb4.x);
        float2 v1 = __half22float2(*(const __half2*)&vb4.y);
        float2 v2 = __half22float2(*(const __half2*)&vb4.z);
        float2 v3 = __half22float2(*(const __half2*)&vb4.w);
        float h0 = fmaxf(u0.x + v0.x, 0.f), h1 = fmaxf(u0.y + v0.y, 0.f);
        float h2 = fmaxf(u1.x + v1.x, 0.f), h3 = fmaxf(u1.y + v1.y, 0.f);
        float h4 = fmaxf(u2.x + v2.x, 0.f), h5 = fmaxf(u2.y + v2.y, 0.f);
        float h6 = fmaxf(u3.x + v3.x, 0.f), h7 = fmaxf(u3.y + v3.y, 0.f);
        pb = fmaf(h0, w0.x, fmaf(h1, w0.y, fmaf(h2, w0.z, h3 * w0.w)));
        pb = fmaf(h4, w1.x, fmaf(h5, w1.y, fmaf(h6, w1.z, fmaf(h7, w1.w, pb))));
    }

#pragma unroll
    for (int off = 8; off > 0; off >>= 1) {
        pa += __shfl_xor_sync(0xffffffffu, pa, off);
        pb += __shfl_xor_sync(0xffffffffu, pb, off);
    }

    if (gl == 0) {
        s_p[gidx * 2]     = pa;
        s_p[gidx * 2 + 1] = pb;
    }
    __syncthreads();

    if (tid < 32) {
        long long eo = e0 + tid;
        if (eo < E) {
            float z = s_p[tid] + __ldg(b2);
            out[eo] = 1.0f / (1.0f + expf(-z));
        }
    }
}

// ---------------------------------------------------------------------------
extern "C" void kernel_launch(void* const* d_in, const int* in_sizes, int n_in,
                              void* d_out, int out_size)
{
    const float* x   = (const float*)d_in[0];
    const void*  ei  = d_in[1];
    const float* W1  = (const float*)d_in[2];
    const float* b1  = (const float*)d_in[3];
    const float* W2  = (const float*)d_in[4];
    const float* b2  = (const float*)d_in[5];
    float* out = (float*)d_out;

    int N = in_sizes[0] / NODE_DIM;   // 100000
    int E = in_sizes[1] / 2;          // 600000

    static int smem_set = 0;
    if (!smem_set) {
        cudaFuncSetAttribute(gemm_mma_kernel,
                             cudaFuncAttributeMaxDynamicSharedMemorySize, SM_TOTAL);
        smem_set = 1;
    }

    gemm_mma_kernel<<<148, 256, SM_TOTAL>>>(x, W1, b1, N);

    int blocks = (E + 31) / 32;
    edge_kernel<<<blocks, 256>>>(ei, W2, b2, out, E, N);
}

// round 13
// speedup vs baseline: 2.7903x; 1.2276x over previous
#include <cuda_runtime.h>
#include <cuda_bf16.h>
#include <cuda_fp16.h>
#include <math.h>
#include <string.h>

#define NODE_DIM 128
#define MAX_NODES 100000

typedef unsigned long long u64;
typedef unsigned int u32;

// Scratch: per-node UV[n] = [u[n]+b1 (128) | v[n] (128)] in fp16, 51.2 MB.
// Columns PERMUTED within each 64-block: p = 16a + 2j + q for c = 2a + 8j + q.
__device__ __align__(16) __half g_UVh[(size_t)MAX_NODES * 256];

// ---------------------------------------------------------------------------
// SMEM layout (dynamic, bytes). A/B rows padded to 136 bf16 (272 B).
//  A hi/lo: 128 x 136 bf16 each; B hi: 256 x 136 bf16; stage: 128 x 132 f32.
// ---------------------------------------------------------------------------
#define KP 136
#define STP 132
#define SM_AHI 0
#define SM_ALO 34816
#define SM_BHI 69632
#define SM_STAGE 139264
#define SM_TOTAL (SM_STAGE + 128 * STP * 4)   // 206848

#define LDSM_X4(r0, r1, r2, r3, addr) \
    asm volatile("ldmatrix.sync.aligned.m8n8.x4.shared.b16 {%0,%1,%2,%3}, [%4];" \
                 : "=r"(r0), "=r"(r1), "=r"(r2), "=r"(r3) : "r"(addr))

#define MMA16816(c, a, b) \
    asm volatile("mma.sync.aligned.m16n8k16.row.col.f32.bf16.bf16.f32 " \
                 "{%0,%1,%2,%3}, {%4,%5,%6,%7}, {%8,%9}, {%0,%1,%2,%3};" \
                 : "+f"((c)[0]), "+f"((c)[1]), "+f"((c)[2]), "+f"((c)[3]) \
                 : "r"((a)[0]), "r"((a)[1]), "r"((a)[2]), "r"((a)[3]), \
                   "r"((b)[0]), "r"((b)[1]))

#define CP_ASYNC16(dst, src, srcsz) \
    asm volatile("cp.async.cg.shared.global [%0], [%1], 16, %2;" \
                 :: "r"(dst), "l"(src), "r"(srcsz) : "memory")
#define CP_COMMIT() asm volatile("cp.async.commit_group;" ::: "memory")
#define CP_WAIT0()  asm volatile("cp.async.wait_group 0;" ::: "memory")

__device__ __forceinline__ u32 smem_u32(const void* p) {
    u32 a;
    asm("{ .reg .u64 t; cvta.to.shared.u64 t, %1; cvt.u32.u64 %0, t; }" : "=r"(a) : "l"(p));
    return a;
}
__device__ __forceinline__ u32 bf2_u32(__nv_bfloat162 v) {
    u32 u; memcpy(&u, &v, 4); return u;
}
__device__ __forceinline__ u64 hi4(float a, float b, float c, float d) {
    return (u64)bf2_u32(__floats2bfloat162_rn(a, b))
         | ((u64)bf2_u32(__floats2bfloat162_rn(c, d)) << 32);
}
__device__ __forceinline__ u32 h2_u32(float a, float b) {
    __half2 h = __floats2half2_rn(a, b);
    u32 u; memcpy(&u, &h, 4); return u;
}

// ---------------------------------------------------------------------------
// Split-bf16 GEMM via mma.sync: UV[N,256] = x[N,128] @ Wcat[128,256]
// 2 passes: Ah*Bh + Al*Bh (B bf16-rounded). A tiles pipelined via cp.async.
// ---------------------------------------------------------------------------
__global__ void __launch_bounds__(256, 1) gemm_mma_kernel(
    const float* __restrict__ x, const float* __restrict__ W1,
    const float* __restrict__ b1, int N)
{
    extern __shared__ char smem[];
    const u32 sb = smem_u32(smem);
    const int tid = threadIdx.x, wid = tid >> 5, lane = tid & 31;

    // ---- B setup (once per CTA): Bh[n][k] = bf16(Wcat[k][n]) ----
    {
        const int n  = tid;
        const int nc = n & 127;
        const int r0 = (n < 128) ? 0 : 128;
        char* bh = smem + SM_BHI + n * (KP * 2);
#pragma unroll 4
        for (int k4 = 0; k4 < 32; ++k4) {
            float v0 = W1[(size_t)(r0 + k4 * 4 + 0) * NODE_DIM + nc];
            float v1 = W1[(size_t)(r0 + k4 * 4 + 1) * NODE_DIM + nc];
            float v2 = W1[(size_t)(r0 + k4 * 4 + 2) * NODE_DIM + nc];
            float v3 = W1[(size_t)(r0 + k4 * 4 + 3) * NODE_DIM + nc];
            *(u64*)(bh + k4 * 8) = hi4(v0, v1, v2, v3);
        }
    }

    const int m0 = (wid & 1) * 64;
    const int n0 = (wid >> 1) * 64;
    const u32 aOffLane = (u32)(((m0 + (lane & 15)) * KP + ((lane >> 4) & 1) * 8) * 2);
    const u32 bOffLane = (u32)(((n0 + ((lane & 16) ? 8 : 0) + (lane & 7)) * KP
                                + ((lane >> 3) & 1) * 8) * 2);
    const u32 aHiB = sb + SM_AHI + aOffLane;
    const u32 aLoB = sb + SM_ALO + aOffLane;
    const u32 bHiB = sb + SM_BHI + bOffLane;

    // b1 pairs for this thread's original columns c = n0 + 2a + 8j + q
    const int aIdx = lane & 3;
    const int cA = n0 + 2 * aIdx;
    float badd[8][2];
#pragma unroll
    for (int j = 0; j < 8; ++j) {
        int c = cA + 8 * j;
        if (c < 128) {
            float2 bv = __ldg((const float2*)&b1[c]);
            badd[j][0] = bv.x; badd[j][1] = bv.y;
        } else {
            badd[j][0] = 0.f; badd[j][1] = 0.f;
        }
    }

    const int tiles = (N + 127) >> 7;

    // ---- Prologue: prefetch first tile (4096 x 16B chunks = full 64 KB) ----
    {
        int t0 = blockIdx.x;
        if (t0 < tiles) {
            const int row0 = t0 * 128;
#pragma unroll
            for (int it = 0; it < 16; ++it) {
                int idx = it * 256 + tid;           // 0..4095
                int r = idx >> 5, c4 = idx & 31;    // row 0..127, 16B-chunk 0..31
                int gr = row0 + r;
                u32 dst = sb + SM_STAGE + (u32)(r * (STP * 4) + c4 * 16);
                const float* src = &x[(size_t)gr * NODE_DIM + c4 * 4];
                CP_ASYNC16(dst, src, (gr < N) ? 16u : 0u);
            }
        }
        CP_COMMIT();
    }

    for (int t = blockIdx.x; t < tiles; t += (int)gridDim.x) {
        const int row0 = t * 128;

        CP_WAIT0();
        __syncthreads();   // staging visible to all; prev mainloop done with sA

        // ---- Convert staging f32 -> sA hi/lo bf16 ----
#pragma unroll 4
        for (int it = 0; it < 16; ++it) {
            int idx = it * 256 + tid;
            int r = idx >> 5, c4 = idx & 31;
            float4 xv = *(const float4*)(smem + SM_STAGE + r * (STP * 4) + c4 * 16);
            float hx = __bfloat162float(__float2bfloat16(xv.x));
            float hy = __bfloat162float(__float2bfloat16(xv.y));
            float hz = __bfloat162float(__float2bfloat16(xv.z));
            float hw = __bfloat162float(__float2bfloat16(xv.w));
            u32 off = (u32)(r * (KP * 2) + c4 * 8);
            *(u64*)(smem + SM_AHI + off) = hi4(xv.x, xv.y, xv.z, xv.w);
            *(u64*)(smem + SM_ALO + off) = hi4(xv.x - hx, xv.y - hy, xv.z - hz, xv.w - hw);
        }
        __syncthreads();

        // ---- Prefetch next tile (overlaps mainloop + epilogue) ----
        {
            int tn = t + (int)gridDim.x;
            if (tn < tiles) {
                const int rown = tn * 128;
#pragma unroll
                for (int it = 0; it < 16; ++it) {
                    int idx = it * 256 + tid;
                    int r = idx >> 5, c4 = idx & 31;
                    int gr = rown + r;
                    u32 dst = sb + SM_STAGE + (u32)(r * (STP * 4) + c4 * 16);
                    const float* src = &x[(size_t)gr * NODE_DIM + c4 * 4];
                    CP_ASYNC16(dst, src, (gr < N) ? 16u : 0u);
                }
            }
            CP_COMMIT();
        }

        // ---- Mainloop: 8 k-steps, 12 LDSM + 64 MMA each ----
        float acc[4][8][4];
#pragma unroll
        for (int i = 0; i < 4; ++i)
#pragma unroll
            for (int j = 0; j < 8; ++j)
#pragma unroll
                for (int q = 0; q < 4; ++q) acc[i][j][q] = 0.0f;

#pragma unroll
        for (int ks = 0; ks < 8; ++ks) {
            const u32 ko = (u32)(ks * 32);

            u32 ah[4][4], bh[8][2];
#pragma unroll
            for (int i = 0; i < 4; ++i)
                LDSM_X4(ah[i][0], ah[i][1], ah[i][2], ah[i][3],
                        aHiB + ko + (u32)(i * 16 * KP * 2));
#pragma unroll
            for (int jj = 0; jj < 4; ++jj)
                LDSM_X4(bh[2 * jj][0], bh[2 * jj][1], bh[2 * jj + 1][0], bh[2 * jj + 1][1],
                        bHiB + ko + (u32)(jj * 16 * KP * 2));
#pragma unroll
            for (int i = 0; i < 4; ++i)
#pragma unroll
                for (int j = 0; j < 8; ++j)
                    MMA16816(acc[i][j], ah[i], bh[j]);

            u32 al[4][4];
#pragma unroll
            for (int i = 0; i < 4; ++i)
                LDSM_X4(al[i][0], al[i][1], al[i][2], al[i][3],
                        aLoB + ko + (u32)(i * 16 * KP * 2));
#pragma unroll
            for (int i = 0; i < 4; ++i)
#pragma unroll
                for (int j = 0; j < 8; ++j)
                    MMA16816(acc[i][j], al[i], bh[j]);
        }

        // ---- Epilogue: +b1, fp16, permuted -> 2x STG.128 per row ----
        const int rA = row0 + m0 + (lane >> 2);
        const u32 colBase = (u32)(n0 + 16 * aIdx);
#pragma unroll
        for (int i = 0; i < 4; ++i) {
#pragma unroll
            for (int half = 0; half < 2; ++half) {
                int r = rA + 16 * i + 8 * half;
                if (r < N) {
                    u32 w[8];
#pragma unroll
                    for (int j = 0; j < 8; ++j)
                        w[j] = h2_u32(acc[i][j][2 * half + 0] + badd[j][0],
                                      acc[i][j][2 * half + 1] + badd[j][1]);
                    __half* dst = &g_UVh[(size_t)r * 256 + colBase];
                    *(uint4*)dst = make_uint4(w[0], w[1], w[2], w[3]);
                    *(uint4*)(dst + 8) = make_uint4(w[4], w[5], w[6], w[7]);
                }
            }
        }
    }
}

// ---------------------------------------------------------------------------
// Edge pass: 2 edges per 16-lane group (4 per warp, 32 per block).
//   h_p = relu(u'[s]_p + v[d]_p);  out = sigmoid(sum_p h_p * W2p[p] + b2)
// ---------------------------------------------------------------------------
__global__ void __launch_bounds__(256) edge_kernel(
    const void* __restrict__ ei_raw,
    const float* __restrict__ W2,
    const float* __restrict__ b2,
    float* __restrict__ out, int E, int N)
{
    __shared__ float s_p[32];
    __shared__ float s_w2p[128];

    const int tid  = threadIdx.x;
    const int wid  = tid >> 5;
    const int lane = tid & 31;
    const int grp  = lane >> 4;
    const int gl   = lane & 15;

    if (tid < 128) {
        int blk = tid >> 6, r = tid & 63;
        int c = blk * 64 + 2 * (r >> 4) + 8 * ((r >> 1) & 7) + (r & 1);
        s_w2p[tid] = __ldg(&W2[c]);
    }

    const long long* p64 = (const long long*)ei_raw;
    long long probe = __ldg(&p64[lane & 15]);
    bool okp = (probe >= 0 && probe < (long long)N);
    bool is64 = (__ballot_sync(0xffffffffu, okp) == 0xffffffffu);

    __syncthreads();

    const long long e0 = (long long)blockIdx.x * 32;
    const int gidx = wid * 2 + grp;
    const int ea = (int)(e0 + gidx * 2);
    const int eb = ea + 1;

    const float4 w0 = *(const float4*)&s_w2p[gl * 8];
    const float4 w1 = *(const float4*)&s_w2p[gl * 8 + 4];

    float pa = 0.0f, pb = 0.0f;

    int sa = 0, da = 0, sc = 0, dc = 0;
    bool va_ = (ea < E), vb_ = (eb < E);
    if (va_) {
        if (is64) {
            sa = (int)__ldg(&p64[ea]);
            da = (int)__ldg(&p64[(size_t)E + ea]);
        } else {
            const int* ei = (const int*)ei_raw;
            sa = __ldg(&ei[ea]);
            da = __ldg(&ei[(size_t)E + ea]);
        }
        sa = min(max(sa, 0), N - 1); da = min(max(da, 0), N - 1);
    }
    if (vb_) {
        if (is64) {
            sc = (int)__ldg(&p64[eb]);
            dc = (int)__ldg(&p64[(size_t)E + eb]);
        } else {
            const int* ei = (const int*)ei_raw;
            sc = __ldg(&ei[eb]);
            dc = __ldg(&ei[(size_t)E + eb]);
        }
        sc = min(max(sc, 0), N - 1); dc = min(max(dc, 0), N - 1);
    }

    uint4 ua4 = make_uint4(0, 0, 0, 0), va4 = ua4, ub4 = ua4, vb4 = ua4;
    if (va_) {
        ua4 = *(const uint4*)&g_UVh[(size_t)sa * 256 + gl * 8];
        va4 = *(const uint4*)&g_UVh[(size_t)da * 256 + 128 + gl * 8];
    }
    if (vb_) {
        ub4 = *(const uint4*)&g_UVh[(size_t)sc * 256 + gl * 8];
        vb4 = *(const uint4*)&g_UVh[(size_t)dc * 256 + 128 + gl * 8];
    }

    {
        float2 u0 = __half22float2(*(const __half2*)&ua4.x);
        float2 u1 = __half22float2(*(const __half2*)&ua4.y);
        float2 u2 = __half22float2(*(const __half2*)&ua4.z);
        float2 u3 = __half22float2(*(const __half2*)&ua4.w);
        float2 v0 = __half22float2(*(const __half2*)&va4.x);
        float2 v1 = __half22float2(*(const __half2*)&va4.y);
        float2 v2 = __half22float2(*(const __half2*)&va4.z);
        float2 v3 = __half22float2(*(const __half2*)&va4.w);
        float h0 = fmaxf(u0.x + v0.x, 0.f), h1 = fmaxf(u0.y + v0.y, 0.f);
        float h2 = fmaxf(u1.x + v1.x, 0.f), h3 = fmaxf(u1.y + v1.y, 0.f);
        float h4 = fmaxf(u2.x + v2.x, 0.f), h5 = fmaxf(u2.y + v2.y, 0.f);
        float h6 = fmaxf(u3.x + v3.x, 0.f), h7 = fmaxf(u3.y + v3.y, 0.f);
        pa = fmaf(h0, w0.x, fmaf(h1, w0.y, fmaf(h2, w0.z, h3 * w0.w)));
        pa = fmaf(h4, w1.x, fmaf(h5, w1.y, fmaf(h6, w1.z, fmaf(h7, w1.w, pa))));
    }
    {
        float2 u0 = __half22float2(*(const __half2*)&ub4.x);
        float2 u1 = __half22float2(*(const __half2*)&ub4.y);
        float2 u2 = __half22float2(*(const __half2*)&ub4.z);
        float2 u3 = __half22float2(*(const __half2*)&ub4.w);
        float2 v0 = __half22float2(*(const __half2*)&vb4.x);
        float2 v1 = __half22float2(*(const __half2*)&vb4.y);
        float2 v2 = __half22float2(*(const __half2*)&vb4.z);
        float2 v3 = __half22float2(*(const __half2*)&vb4.w);
        float h0 = fmaxf(u0.x + v0.x, 0.f), h1 = fmaxf(u0.y + v0.y, 0.f);
        float h2 = fmaxf(u1.x + v1.x, 0.f), h3 = fmaxf(u1.y + v1.y, 0.f);
        float h4 = fmaxf(u2.x + v2.x, 0.f), h5 = fmaxf(u2.y + v2.y, 0.f);
        float h6 = fmaxf(u3.x + v3.x, 0.f), h7 = fmaxf(u3.y + v3.y, 0.f);
        pb = fmaf(h0, w0.x, fmaf(h1, w0.y, fmaf(h2, w0.z, h3 * w0.w)));
        pb = fmaf(h4, w1.x, fmaf(h5, w1.y, fmaf(h6, w1.z, fmaf(h7, w1.w, pb))));
    }

#pragma unroll
    for (int off = 8; off > 0; off >>= 1) {
        pa += __shfl_xor_sync(0xffffffffu, pa, off);
        pb += __shfl_xor_sync(0xffffffffu, pb, off);
    }

    if (gl == 0) {
        s_p[gidx * 2]     = pa;
        s_p[gidx * 2 + 1] = pb;
    }
    __syncthreads();

    if (tid < 32) {
        long long eo = e0 + tid;
        if (eo < E) {
            float z = s_p[tid] + __ldg(b2);
            out[eo] = 1.0f / (1.0f + expf(-z));
        }
    }
}

// ---------------------------------------------------------------------------
extern "C" void kernel_launch(void* const* d_in, const int* in_sizes, int n_in,
                              void* d_out, int out_size)
{
    const float* x   = (const float*)d_in[0];
    const void*  ei  = d_in[1];
    const float* W1  = (const float*)d_in[2];
    const float* b1  = (const float*)d_in[3];
    const float* W2  = (const float*)d_in[4];
    const float* b2  = (const float*)d_in[5];
    float* out = (float*)d_out;

    int N = in_sizes[0] / NODE_DIM;   // 100000
    int E = in_sizes[1] / 2;          // 600000

    static int smem_set = 0;
    if (!smem_set) {
        cudaFuncSetAttribute(gemm_mma_kernel,
                             cudaFuncAttributeMaxDynamicSharedMemorySize, SM_TOTAL);
        smem_set = 1;
    }

    gemm_mma_kernel<<<148, 256, SM_TOTAL>>>(x, W1, b1, N);

    int blocks = (E + 31) / 32;
    edge_kernel<<<blocks, 256>>>(ei, W2, b2, out, E, N);
}

// round 14
// speedup vs baseline: 3.3531x; 1.2017x over previous
#include <cuda_runtime.h>
#include <cuda_fp16.h>
#include <math.h>
#include <string.h>

#define NODE_DIM 128
#define MAX_NODES 100000

typedef unsigned long long u64;
typedef unsigned int u32;

// Scratch: per-node UV[n] = [u[n]+b1 (128) | v[n] (128)] in fp16, 51.2 MB.
// Columns PERMUTED within each 64-block: p = 16a + 2j + q for c = 2a + 8j + q.
__device__ __align__(16) __half g_UVh[(size_t)MAX_NODES * 256];

// ---------------------------------------------------------------------------
// SMEM layout (dynamic, bytes). A/B rows padded to 136 fp16 (272 B).
//  A: 128 x 136 fp16; B: 256 x 136 fp16; stage: 128 x 132 f32.
// ---------------------------------------------------------------------------
#define KP 136
#define STP 132
#define SM_A 0
#define SM_B 34816
#define SM_STAGE 104448
#define SM_TOTAL (SM_STAGE + 128 * STP * 4)   // 172032

#define LDSM_X4(r0, r1, r2, r3, addr) \
    asm volatile("ldmatrix.sync.aligned.m8n8.x4.shared.b16 {%0,%1,%2,%3}, [%4];" \
                 : "=r"(r0), "=r"(r1), "=r"(r2), "=r"(r3) : "r"(addr))

#define MMA16816F16(c, a, b) \
    asm volatile("mma.sync.aligned.m16n8k16.row.col.f32.f16.f16.f32 " \
                 "{%0,%1,%2,%3}, {%4,%5,%6,%7}, {%8,%9}, {%0,%1,%2,%3};" \
                 : "+f"((c)[0]), "+f"((c)[1]), "+f"((c)[2]), "+f"((c)[3]) \
                 : "r"((a)[0]), "r"((a)[1]), "r"((a)[2]), "r"((a)[3]), \
                   "r"((b)[0]), "r"((b)[1]))

#define CP_ASYNC16(dst, src, srcsz) \
    asm volatile("cp.async.cg.shared.global [%0], [%1], 16, %2;" \
                 :: "r"(dst), "l"(src), "r"(srcsz) : "memory")
#define CP_COMMIT() asm volatile("cp.async.commit_group;" ::: "memory")
#define CP_WAIT0()  asm volatile("cp.async.wait_group 0;" ::: "memory")

__device__ __forceinline__ u32 smem_u32(const void* p) {
    u32 a;
    asm("{ .reg .u64 t; cvta.to.shared.u64 t, %1; cvt.u32.u64 %0, t; }" : "=r"(a) : "l"(p));
    return a;
}
__device__ __forceinline__ u32 h2u(__half2 v) {
    u32 u; memcpy(&u, &v, 4); return u;
}
__device__ __forceinline__ u64 h4(float a, float b, float c, float d) {
    return (u64)h2u(__floats2half2_rn(a, b))
         | ((u64)h2u(__floats2half2_rn(c, d)) << 32);
}
__device__ __forceinline__ u32 h2_u32(float a, float b) {
    __half2 h = __floats2half2_rn(a, b);
    u32 u; memcpy(&u, &h, 4); return u;
}

// ---------------------------------------------------------------------------
// fp16 GEMM via mma.sync: UV[N,256] = x[N,128] @ Wcat[128,256]
// Single pass, fp16 operands, fp32 accum. A tiles pipelined via cp.async.
// ---------------------------------------------------------------------------
__global__ void __launch_bounds__(256, 1) gemm_mma_kernel(
    const float* __restrict__ x, const float* __restrict__ W1,
    const float* __restrict__ b1, int N)
{
    extern __shared__ char smem[];
    const u32 sb = smem_u32(smem);
    const int tid = threadIdx.x, wid = tid >> 5, lane = tid & 31;

    // ---- B setup (once per CTA): B[n][k] = fp16(Wcat[k][n]) ----
    {
        const int n  = tid;
        const int nc = n & 127;
        const int r0 = (n < 128) ? 0 : 128;
        char* bp = smem + SM_B + n * (KP * 2);
#pragma unroll 4
        for (int k4 = 0; k4 < 32; ++k4) {
            float v0 = W1[(size_t)(r0 + k4 * 4 + 0) * NODE_DIM + nc];
            float v1 = W1[(size_t)(r0 + k4 * 4 + 1) * NODE_DIM + nc];
            float v2 = W1[(size_t)(r0 + k4 * 4 + 2) * NODE_DIM + nc];
            float v3 = W1[(size_t)(r0 + k4 * 4 + 3) * NODE_DIM + nc];
            *(u64*)(bp + k4 * 8) = h4(v0, v1, v2, v3);
        }
    }

    const int m0 = (wid & 1) * 64;
    const int n0 = (wid >> 1) * 64;
    const u32 aOffLane = (u32)(((m0 + (lane & 15)) * KP + ((lane >> 4) & 1) * 8) * 2);
    const u32 bOffLane = (u32)(((n0 + ((lane & 16) ? 8 : 0) + (lane & 7)) * KP
                                + ((lane >> 3) & 1) * 8) * 2);
    const u32 aB = sb + SM_A + aOffLane;
    const u32 bB = sb + SM_B + bOffLane;

    // b1 pairs for this thread's original columns c = n0 + 2a + 8j + q
    const int aIdx = lane & 3;
    const int cA = n0 + 2 * aIdx;
    float badd[8][2];
#pragma unroll
    for (int j = 0; j < 8; ++j) {
        int c = cA + 8 * j;
        if (c < 128) {
            float2 bv = __ldg((const float2*)&b1[c]);
            badd[j][0] = bv.x; badd[j][1] = bv.y;
        } else {
            badd[j][0] = 0.f; badd[j][1] = 0.f;
        }
    }

    const int tiles = (N + 127) >> 7;

    // ---- Prologue: prefetch first tile (4096 x 16B chunks = full 64 KB) ----
    {
        int t0 = blockIdx.x;
        if (t0 < tiles) {
            const int row0 = t0 * 128;
#pragma unroll
            for (int it = 0; it < 16; ++it) {
                int idx = it * 256 + tid;           // 0..4095
                int r = idx >> 5, c4 = idx & 31;    // row 0..127, 16B-chunk 0..31
                int gr = row0 + r;
                u32 dst = sb + SM_STAGE + (u32)(r * (STP * 4) + c4 * 16);
                const float* src = &x[(size_t)gr * NODE_DIM + c4 * 4];
                CP_ASYNC16(dst, src, (gr < N) ? 16u : 0u);
            }
        }
        CP_COMMIT();
    }

    for (int t = blockIdx.x; t < tiles; t += (int)gridDim.x) {
        const int row0 = t * 128;

        CP_WAIT0();
        __syncthreads();   // staging visible to all; prev mainloop done with sA

        // ---- Convert staging f32 -> sA fp16 ----
#pragma unroll 4
        for (int it = 0; it < 16; ++it) {
            int idx = it * 256 + tid;
            int r = idx >> 5, c4 = idx & 31;
            float4 xv = *(const float4*)(smem + SM_STAGE + r * (STP * 4) + c4 * 16);
            u32 off = (u32)(r * (KP * 2) + c4 * 8);
            *(u64*)(smem + SM_A + off) = h4(xv.x, xv.y, xv.z, xv.w);
        }
        __syncthreads();

        // ---- Prefetch next tile (overlaps mainloop + epilogue) ----
        {
            int tn = t + (int)gridDim.x;
            if (tn < tiles) {
                const int rown = tn * 128;
#pragma unroll
                for (int it = 0; it < 16; ++it) {
                    int idx = it * 256 + tid;
                    int r = idx >> 5, c4 = idx & 31;
                    int gr = rown + r;
                    u32 dst = sb + SM_STAGE + (u32)(r * (STP * 4) + c4 * 16);
                    const float* src = &x[(size_t)gr * NODE_DIM + c4 * 4];
                    CP_ASYNC16(dst, src, (gr < N) ? 16u : 0u);
                }
            }
            CP_COMMIT();
        }

        // ---- Mainloop: 8 k-steps, 8 LDSM + 32 MMA each ----
        float acc[4][8][4];
#pragma unroll
        for (int i = 0; i < 4; ++i)
#pragma unroll
            for (int j = 0; j < 8; ++j)
#pragma unroll
                for (int q = 0; q < 4; ++q) acc[i][j][q] = 0.0f;

#pragma unroll
        for (int ks = 0; ks < 8; ++ks) {
            const u32 ko = (u32)(ks * 32);

            u32 a[4][4], b[8][2];
#pragma unroll
            for (int i = 0; i < 4; ++i)
                LDSM_X4(a[i][0], a[i][1], a[i][2], a[i][3],
                        aB + ko + (u32)(i * 16 * KP * 2));
#pragma unroll
            for (int jj = 0; jj < 4; ++jj)
                LDSM_X4(b[2 * jj][0], b[2 * jj][1], b[2 * jj + 1][0], b[2 * jj + 1][1],
                        bB + ko + (u32)(jj * 16 * KP * 2));
#pragma unroll
            for (int i = 0; i < 4; ++i)
#pragma unroll
                for (int j = 0; j < 8; ++j)
                    MMA16816F16(acc[i][j], a[i], b[j]);
        }

        // ---- Epilogue: +b1, fp16, permuted -> 2x STG.128 per row ----
        const int rA = row0 + m0 + (lane >> 2);
        const u32 colBase = (u32)(n0 + 16 * aIdx);
#pragma unroll
        for (int i = 0; i < 4; ++i) {
#pragma unroll
            for (int half = 0; half < 2; ++half) {
                int r = rA + 16 * i + 8 * half;
                if (r < N) {
                    u32 w[8];
#pragma unroll
                    for (int j = 0; j < 8; ++j)
                        w[j] = h2_u32(acc[i][j][2 * half + 0] + badd[j][0],
                                      acc[i][j][2 * half + 1] + badd[j][1]);
                    __half* dst = &g_UVh[(size_t)r * 256 + colBase];
                    *(uint4*)dst = make_uint4(w[0], w[1], w[2], w[3]);
                    *(uint4*)(dst + 8) = make_uint4(w[4], w[5], w[6], w[7]);
                }
            }
        }
    }
}

// ---------------------------------------------------------------------------
// Edge pass: 2 edges per 16-lane group (4 per warp, 32 per block).
//   h_p = relu(u'[s]_p + v[d]_p);  out = sigmoid(sum_p h_p * W2p[p] + b2)
// ---------------------------------------------------------------------------
__global__ void __launch_bounds__(256) edge_kernel(
    const void* __restrict__ ei_raw,
    const float* __restrict__ W2,
    const float* __restrict__ b2,
    float* __restrict__ out, int E, int N)
{
    __shared__ float s_p[32];
    __shared__ float s_w2p[128];

    const int tid  = threadIdx.x;
    const int wid  = tid >> 5;
    const int lane = tid & 31;
    const int grp  = lane >> 4;
    const int gl   = lane & 15;

    if (tid < 128) {
        int blk = tid >> 6, r = tid & 63;
        int c = blk * 64 + 2 * (r >> 4) + 8 * ((r >> 1) & 7) + (r & 1);
        s_w2p[tid] = __ldg(&W2[c]);
    }

    const long long* p64 = (const long long*)ei_raw;
    long long probe = __ldg(&p64[lane & 15]);
    bool okp = (probe >= 0 && probe < (long long)N);
    bool is64 = (__ballot_sync(0xffffffffu, okp) == 0xffffffffu);

    __syncthreads();

    const long long e0 = (long long)blockIdx.x * 32;
    const int gidx = wid * 2 + grp;
    const int ea = (int)(e0 + gidx * 2);
    const int eb = ea + 1;

    const float4 w0 = *(const float4*)&s_w2p[gl * 8];
    const float4 w1 = *(const float4*)&s_w2p[gl * 8 + 4];

    float pa = 0.0f, pb = 0.0f;

    int sa = 0, da = 0, sc = 0, dc = 0;
    bool va_ = (ea < E), vb_ = (eb < E);
    if (va_) {
        if (is64) {
            sa = (int)__ldg(&p64[ea]);
            da = (int)__ldg(&p64[(size_t)E + ea]);
        } else {
            const int* ei = (const int*)ei_raw;
            sa = __ldg(&ei[ea]);
            da = __ldg(&ei[(size_t)E + ea]);
        }
        sa = min(max(sa, 0), N - 1); da = min(max(da, 0), N - 1);
    }
    if (vb_) {
        if (is64) {
            sc = (int)__ldg(&p64[eb]);
            dc = (int)__ldg(&p64[(size_t)E + eb]);
        } else {
            const int* ei = (const int*)ei_raw;
            sc = __ldg(&ei[eb]);
            dc = __ldg(&ei[(size_t)E + eb]);
        }
        sc = min(max(sc, 0), N - 1); dc = min(max(dc, 0), N - 1);
    }

    uint4 ua4 = make_uint4(0, 0, 0, 0), va4 = ua4, ub4 = ua4, vb4 = ua4;
    if (va_) {
        ua4 = *(const uint4*)&g_UVh[(size_t)sa * 256 + gl * 8];
        va4 = *(const uint4*)&g_UVh[(size_t)da * 256 + 128 + gl * 8];
    }
    if (vb_) {
        ub4 = *(const uint4*)&g_UVh[(size_t)sc * 256 + gl * 8];
        vb4 = *(const uint4*)&g_UVh[(size_t)dc * 256 + 128 + gl * 8];
    }

    {
        float2 u0 = __half22float2(*(const __half2*)&ua4.x);
        float2 u1 = __half22float2(*(const __half2*)&ua4.y);
        float2 u2 = __half22float2(*(const __half2*)&ua4.z);
        float2 u3 = __half22float2(*(const __half2*)&ua4.w);
        float2 v0 = __half22float2(*(const __half2*)&va4.x);
        float2 v1 = __half22float2(*(const __half2*)&va4.y);
        float2 v2 = __half22float2(*(const __half2*)&va4.z);
        float2 v3 = __half22float2(*(const __half2*)&va4.w);
        float h0 = fmaxf(u0.x + v0.x, 0.f), h1 = fmaxf(u0.y + v0.y, 0.f);
        float h2 = fmaxf(u1.x + v1.x, 0.f), h3 = fmaxf(u1.y + v1.y, 0.f);
        float h4 = fmaxf(u2.x + v2.x, 0.f), h5 = fmaxf(u2.y + v2.y, 0.f);
        float h6 = fmaxf(u3.x + v3.x, 0.f), h7 = fmaxf(u3.y + v3.y, 0.f);
        pa = fmaf(h0, w0.x, fmaf(h1, w0.y, fmaf(h2, w0.z, h3 * w0.w)));
        pa = fmaf(h4, w1.x, fmaf(h5, w1.y, fmaf(h6, w1.z, fmaf(h7, w1.w, pa))));
    }
    {
        float2 u0 = __half22float2(*(const __half2*)&ub4.x);
        float2 u1 = __half22float2(*(const __half2*)&ub4.y);
        float2 u2 = __half22float2(*(const __half2*)&ub4.z);
        float2 u3 = __half22float2(*(const __half2*)&ub4.w);
        float2 v0 = __half22float2(*(const __half2*)&vb4.x);
        float2 v1 = __half22float2(*(const __half2*)&vb4.y);
        float2 v2 = __half22float2(*(const __half2*)&vb4.z);
        float2 v3 = __half22float2(*(const __half2*)&vb4.w);
        float h0 = fmaxf(u0.x + v0.x, 0.f), h1 = fmaxf(u0.y + v0.y, 0.f);
        float h2 = fmaxf(u1.x + v1.x, 0.f), h3 = fmaxf(u1.y + v1.y, 0.f);
        float h4 = fmaxf(u2.x + v2.x, 0.f), h5 = fmaxf(u2.y + v2.y, 0.f);
        float h6 = fmaxf(u3.x + v3.x, 0.f), h7 = fmaxf(u3.y + v3.y, 0.f);
        pb = fmaf(h0, w0.x, fmaf(h1, w0.y, fmaf(h2, w0.z, h3 * w0.w)));
        pb = fmaf(h4, w1.x, fmaf(h5, w1.y, fmaf(h6, w1.z, fmaf(h7, w1.w, pb))));
    }

#pragma unroll
    for (int off = 8; off > 0; off >>= 1) {
        pa += __shfl_xor_sync(0xffffffffu, pa, off);
        pb += __shfl_xor_sync(0xffffffffu, pb, off);
    }

    if (gl == 0) {
        s_p[gidx * 2]     = pa;
        s_p[gidx * 2 + 1] = pb;
    }
    __syncthreads();

    if (tid < 32) {
        long long eo = e0 + tid;
        if (eo < E) {
            float z = s_p[tid] + __ldg(b2);
            out[eo] = 1.0f / (1.0f + expf(-z));
        }
    }
}

// ---------------------------------------------------------------------------
extern "C" void kernel_launch(void* const* d_in, const int* in_sizes, int n_in,
                              void* d_out, int out_size)
{
    const float* x   = (const float*)d_in[0];
    const void*  ei  = d_in[1];
    const float* W1  = (const float*)d_in[2];
    const float* b1  = (const float*)d_in[3];
    const float* W2  = (const float*)d_in[4];
    const float* b2  = (const float*)d_in[5];
    float* out = (float*)d_out;

    int N = in_sizes[0] / NODE_DIM;   // 100000
    int E = in_sizes[1] / 2;          // 600000

    static int smem_set = 0;
    if (!smem_set) {
        cudaFuncSetAttribute(gemm_mma_kernel,
                             cudaFuncAttributeMaxDynamicSharedMemorySize, SM_TOTAL);
        smem_set = 1;
    }

    gemm_mma_kernel<<<148, 256, SM_TOTAL>>>(x, W1, b1, N);

    int blocks = (E + 31) / 32;
    edge_kernel<<<blocks, 256>>>(ei, W2, b2, out, E, N);
}

// round 15
// speedup vs baseline: 3.4063x; 1.0159x over previous
#include <cuda_runtime.h>
#include <cuda_fp16.h>
#include <math.h>
#include <string.h>

#define NODE_DIM 128
#define MAX_NODES 100000

typedef unsigned long long u64;
typedef unsigned int u32;

// Scratch: per-node UV[n] = [u[n]+b1 (128) | v[n] (128)] in fp16, 51.2 MB.
// Columns PERMUTED within each 64-block: p = 16a + 2j + q for c = 2a + 8j + q.
__device__ __align__(16) __half g_UVh[(size_t)MAX_NODES * 256];

// ---------------------------------------------------------------------------
// SMEM layout (dynamic, bytes). A/B rows padded to 136 fp16 (272 B).
// ---------------------------------------------------------------------------
#define KP 136
#define STP 132
#define SM_A 0
#define SM_B 34816
#define SM_STAGE 104448
#define SM_TOTAL (SM_STAGE + 128 * STP * 4)   // 172032

#define LDSM_X4(r0, r1, r2, r3, addr) \
    asm volatile("ldmatrix.sync.aligned.m8n8.x4.shared.b16 {%0,%1,%2,%3}, [%4];" \
                 : "=r"(r0), "=r"(r1), "=r"(r2), "=r"(r3) : "r"(addr))

#define MMA16816F16(c, a, b) \
    asm volatile("mma.sync.aligned.m16n8k16.row.col.f32.f16.f16.f32 " \
                 "{%0,%1,%2,%3}, {%4,%5,%6,%7}, {%8,%9}, {%0,%1,%2,%3};" \
                 : "+f"((c)[0]), "+f"((c)[1]), "+f"((c)[2]), "+f"((c)[3]) \
                 : "r"((a)[0]), "r"((a)[1]), "r"((a)[2]), "r"((a)[3]), \
                   "r"((b)[0]), "r"((b)[1]))

#define CP_ASYNC16(dst, src, srcsz) \
    asm volatile("cp.async.cg.shared.global [%0], [%1], 16, %2;" \
                 :: "r"(dst), "l"(src), "r"(srcsz) : "memory")
#define CP_COMMIT() asm volatile("cp.async.commit_group;" ::: "memory")
#define CP_WAIT0()  asm volatile("cp.async.wait_group 0;" ::: "memory")

__device__ __forceinline__ u32 smem_u32(const void* p) {
    u32 a;
    asm("{ .reg .u64 t; cvta.to.shared.u64 t, %1; cvt.u32.u64 %0, t; }" : "=r"(a) : "l"(p));
    return a;
}
__device__ __forceinline__ u32 h2u(__half2 v) {
    u32 u; memcpy(&u, &v, 4); return u;
}
__device__ __forceinline__ __half2 u2h(u32 u) {
    __half2 h; memcpy(&h, &u, 4); return h;
}
__device__ __forceinline__ u64 h4(float a, float b, float c, float d) {
    return (u64)h2u(__floats2half2_rn(a, b))
         | ((u64)h2u(__floats2half2_rn(c, d)) << 32);
}
__device__ __forceinline__ u32 h2_u32(float a, float b) {
    return h2u(__floats2half2_rn(a, b));
}

// ---------------------------------------------------------------------------
// fp16 GEMM via mma.sync: UV[N,256] = x[N,128] @ Wcat[128,256]
// Single pass, fp16 operands, fp32 accum. A tiles pipelined via cp.async.
// ---------------------------------------------------------------------------
__global__ void __launch_bounds__(256, 1) gemm_mma_kernel(
    const float* __restrict__ x, const float* __restrict__ W1,
    const float* __restrict__ b1, int N)
{
    extern __shared__ char smem[];
    const u32 sb = smem_u32(smem);
    const int tid = threadIdx.x, wid = tid >> 5, lane = tid & 31;

    // ---- B setup (once per CTA): B[n][k] = fp16(Wcat[k][n]) ----
    {
        const int n  = tid;
        const int nc = n & 127;
        const int r0 = (n < 128) ? 0 : 128;
        char* bp = smem + SM_B + n * (KP * 2);
#pragma unroll 4
        for (int k4 = 0; k4 < 32; ++k4) {
            float v0 = W1[(size_t)(r0 + k4 * 4 + 0) * NODE_DIM + nc];
            float v1 = W1[(size_t)(r0 + k4 * 4 + 1) * NODE_DIM + nc];
            float v2 = W1[(size_t)(r0 + k4 * 4 + 2) * NODE_DIM + nc];
            float v3 = W1[(size_t)(r0 + k4 * 4 + 3) * NODE_DIM + nc];
            *(u64*)(bp + k4 * 8) = h4(v0, v1, v2, v3);
        }
    }

    const int m0 = (wid & 1) * 64;
    const int n0 = (wid >> 1) * 64;
    const u32 aOffLane = (u32)(((m0 + (lane & 15)) * KP + ((lane >> 4) & 1) * 8) * 2);
    const u32 bOffLane = (u32)(((n0 + ((lane & 16) ? 8 : 0) + (lane & 7)) * KP
                                + ((lane >> 3) & 1) * 8) * 2);
    const u32 aB = sb + SM_A + aOffLane;
    const u32 bB = sb + SM_B + bOffLane;

    const int aIdx = lane & 3;
    const int cA = n0 + 2 * aIdx;
    float badd[8][2];
#pragma unroll
    for (int j = 0; j < 8; ++j) {
        int c = cA + 8 * j;
        if (c < 128) {
            float2 bv = __ldg((const float2*)&b1[c]);
            badd[j][0] = bv.x; badd[j][1] = bv.y;
        } else {
            badd[j][0] = 0.f; badd[j][1] = 0.f;
        }
    }

    const int tiles = (N + 127) >> 7;

    // ---- Prologue: prefetch first tile ----
    {
        int t0 = blockIdx.x;
        if (t0 < tiles) {
            const int row0 = t0 * 128;
#pragma unroll
            for (int it = 0; it < 16; ++it) {
                int idx = it * 256 + tid;
                int r = idx >> 5, c4 = idx & 31;
                int gr = row0 + r;
                u32 dst = sb + SM_STAGE + (u32)(r * (STP * 4) + c4 * 16);
                const float* src = &x[(size_t)gr * NODE_DIM + c4 * 4];
                CP_ASYNC16(dst, src, (gr < N) ? 16u : 0u);
            }
        }
        CP_COMMIT();
    }

    for (int t = blockIdx.x; t < tiles; t += (int)gridDim.x) {
        const int row0 = t * 128;

        CP_WAIT0();
        __syncthreads();

        // ---- Convert staging f32 -> sA fp16 ----
#pragma unroll 4
        for (int it = 0; it < 16; ++it) {
            int idx = it * 256 + tid;
            int r = idx >> 5, c4 = idx & 31;
            float4 xv = *(const float4*)(smem + SM_STAGE + r * (STP * 4) + c4 * 16);
            u32 off = (u32)(r * (KP * 2) + c4 * 8);
            *(u64*)(smem + SM_A + off) = h4(xv.x, xv.y, xv.z, xv.w);
        }
        __syncthreads();

        // ---- Prefetch next tile ----
        {
            int tn = t + (int)gridDim.x;
            if (tn < tiles) {
                const int rown = tn * 128;
#pragma unroll
                for (int it = 0; it < 16; ++it) {
                    int idx = it * 256 + tid;
                    int r = idx >> 5, c4 = idx & 31;
                    int gr = rown + r;
                    u32 dst = sb + SM_STAGE + (u32)(r * (STP * 4) + c4 * 16);
                    const float* src = &x[(size_t)gr * NODE_DIM + c4 * 4];
                    CP_ASYNC16(dst, src, (gr < N) ? 16u : 0u);
                }
            }
            CP_COMMIT();
        }

        // ---- Mainloop: 8 k-steps, 8 LDSM + 32 MMA each ----
        float acc[4][8][4];
#pragma unroll
        for (int i = 0; i < 4; ++i)
#pragma unroll
            for (int j = 0; j < 8; ++j)
#pragma unroll
                for (int q = 0; q < 4; ++q) acc[i][j][q] = 0.0f;

#pragma unroll
        for (int ks = 0; ks < 8; ++ks) {
            const u32 ko = (u32)(ks * 32);

            u32 a[4][4], b[8][2];
#pragma unroll
            for (int i = 0; i < 4; ++i)
                LDSM_X4(a[i][0], a[i][1], a[i][2], a[i][3],
                        aB + ko + (u32)(i * 16 * KP * 2));
#pragma unroll
            for (int jj = 0; jj < 4; ++jj)
                LDSM_X4(b[2 * jj][0], b[2 * jj][1], b[2 * jj + 1][0], b[2 * jj + 1][1],
                        bB + ko + (u32)(jj * 16 * KP * 2));
#pragma unroll
            for (int i = 0; i < 4; ++i)
#pragma unroll
                for (int j = 0; j < 8; ++j)
                    MMA16816F16(acc[i][j], a[i], b[j]);
        }

        // ---- Epilogue: +b1, fp16, permuted -> 2x STG.128 per row ----
        const int rA = row0 + m0 + (lane >> 2);
        const u32 colBase = (u32)(n0 + 16 * aIdx);
#pragma unroll
        for (int i = 0; i < 4; ++i) {
#pragma unroll
            for (int half = 0; half < 2; ++half) {
                int r = rA + 16 * i + 8 * half;
                if (r < N) {
                    u32 w[8];
#pragma unroll
                    for (int j = 0; j < 8; ++j)
                        w[j] = h2_u32(acc[i][j][2 * half + 0] + badd[j][0],
                                      acc[i][j][2 * half + 1] + badd[j][1]);
                    __half* dst = &g_UVh[(size_t)r * 256 + colBase];
                    *(uint4*)dst = make_uint4(w[0], w[1], w[2], w[3]);
                    *(uint4*)(dst + 8) = make_uint4(w[4], w[5], w[6], w[7]);
                }
            }
        }
    }
}

// ---------------------------------------------------------------------------
// Edge pass: 2 edges per 16-lane group. half2 math throughout:
//   h = hmax2(hadd2(u,v),0); dot via 2 short HFMA2 chains; fp32 reduce.
// s_w2h[i(blk*32+i)] = half2(W2[c0], W2[c0+1]) with c0 = blk*64+2*(i>>3)+8*(i&7)
// (consecutive permuted channels are consecutive original channels).
// ---------------------------------------------------------------------------
__global__ void __launch_bounds__(256) edge_kernel(
    const void* __restrict__ ei_raw,
    const float* __restrict__ W2,
    const float* __restrict__ b2,
    float* __restrict__ out, int E, int N)
{
    __shared__ float s_p[32];
    __shared__ u32 s_w2h[64];

    const int tid  = threadIdx.x;
    const int wid  = tid >> 5;
    const int lane = tid & 31;
    const int grp  = lane >> 4;
    const int gl   = lane & 15;

    if (tid < 64) {
        int blk = tid >> 5, i = tid & 31;
        int c0 = blk * 64 + 2 * (i >> 3) + 8 * (i & 7);
        s_w2h[tid] = h2u(__floats2half2_rn(__ldg(&W2[c0]), __ldg(&W2[c0 + 1])));
    }

    const long long* p64 = (const long long*)ei_raw;
    long long probe = __ldg(&p64[lane & 15]);
    bool okp = (probe >= 0 && probe < (long long)N);
    bool is64 = (__ballot_sync(0xffffffffu, okp) == 0xffffffffu);

    __syncthreads();

    const long long e0 = (long long)blockIdx.x * 32;
    const int gidx = wid * 2 + grp;
    const int ea = (int)(e0 + gidx * 2);
    const int eb = ea + 1;

    const uint4 wv = *(const uint4*)&s_w2h[gl * 4];
    const __half2 zero = u2h(0u);

    float pa = 0.0f, pb = 0.0f;

    int sa = 0, da = 0, sc = 0, dc = 0;
    bool va_ = (ea < E), vb_ = (eb < E);
    if (va_) {
        if (is64) {
            sa = (int)__ldg(&p64[ea]);
            da = (int)__ldg(&p64[(size_t)E + ea]);
        } else {
            const int* ei = (const int*)ei_raw;
            sa = __ldg(&ei[ea]);
            da = __ldg(&ei[(size_t)E + ea]);
        }
        sa = min(max(sa, 0), N - 1); da = min(max(da, 0), N - 1);
    }
    if (vb_) {
        if (is64) {
            sc = (int)__ldg(&p64[eb]);
            dc = (int)__ldg(&p64[(size_t)E + eb]);
        } else {
            const int* ei = (const int*)ei_raw;
            sc = __ldg(&ei[eb]);
            dc = __ldg(&ei[(size_t)E + eb]);
        }
        sc = min(max(sc, 0), N - 1); dc = min(max(dc, 0), N - 1);
    }

    const u32 gl8 = (u32)(gl * 8);
    uint4 ua4 = make_uint4(0, 0, 0, 0), va4 = ua4, ub4 = ua4, vb4 = ua4;
    if (va_) {
        ua4 = *(const uint4*)&g_UVh[(u32)sa * 256u + gl8];
        va4 = *(const uint4*)&g_UVh[(u32)da * 256u + 128u + gl8];
    }
    if (vb_) {
        ub4 = *(const uint4*)&g_UVh[(u32)sc * 256u + gl8];
        vb4 = *(const uint4*)&g_UVh[(u32)dc * 256u + 128u + gl8];
    }

    {
        __half2 h0 = __hmax2(__hadd2(u2h(ua4.x), u2h(va4.x)), zero);
        __half2 h1 = __hmax2(__hadd2(u2h(ua4.y), u2h(va4.y)), zero);
        __half2 h2 = __hmax2(__hadd2(u2h(ua4.z), u2h(va4.z)), zero);
        __half2 h3 = __hmax2(__hadd2(u2h(ua4.w), u2h(va4.w)), zero);
        __half2 acc0 = __hfma2(h1, u2h(wv.y), __hmul2(h0, u2h(wv.x)));
        __half2 acc1 = __hfma2(h3, u2h(wv.w), __hmul2(h2, u2h(wv.z)));
        float2 f0 = __half22float2(acc0);
        float2 f1 = __half22float2(acc1);
        pa = (f0.x + f0.y) + (f1.x + f1.y);
    }
    {
        __half2 h0 = __hmax2(__hadd2(u2h(ub4.x), u2h(vb4.x)), zero);
        __half2 h1 = __hmax2(__hadd2(u2h(ub4.y), u2h(vb4.y)), zero);
        __half2 h2 = __hmax2(__hadd2(u2h(ub4.z), u2h(vb4.z)), zero);
        __half2 h3 = __hmax2(__hadd2(u2h(ub4.w), u2h(vb4.w)), zero);
        __half2 acc0 = __hfma2(h1, u2h(wv.y), __hmul2(h0, u2h(wv.x)));
        __half2 acc1 = __hfma2(h3, u2h(wv.w), __hmul2(h2, u2h(wv.z)));
        float2 f0 = __half22float2(acc0);
        float2 f1 = __half22float2(acc1);
        pb = (f0.x + f0.y) + (f1.x + f1.y);
    }

#pragma unroll
    for (int off = 8; off > 0; off >>= 1) {
        pa += __shfl_xor_sync(0xffffffffu, pa, off);
        pb += __shfl_xor_sync(0xffffffffu, pb, off);
    }

    if (gl == 0) {
        s_p[gidx * 2]     = pa;
        s_p[gidx * 2 + 1] = pb;
    }
    __syncthreads();

    if (tid < 32) {
        long long eo = e0 + tid;
        if (eo < E) {
            float z = s_p[tid] + __ldg(b2);
            out[eo] = 1.0f / (1.0f + expf(-z));
        }
    }
}

// ---------------------------------------------------------------------------
extern "C" void kernel_launch(void* const* d_in, const int* in_sizes, int n_in,
                              void* d_out, int out_size)
{
    const float* x   = (const float*)d_in[0];
    const void*  ei  = d_in[1];
    const float* W1  = (const float*)d_in[2];
    const float* b1  = (const float*)d_in[3];
    const float* W2  = (const float*)d_in[4];
    const float* b2  = (const float*)d_in[5];
    float* out = (float*)d_out;

    int N = in_sizes[0] / NODE_DIM;   // 100000
    int E = in_sizes[1] / 2;          // 600000

    static int smem_set = 0;
    if (!smem_set) {
        cudaFuncSetAttribute(gemm_mma_kernel,
                             cudaFuncAttributeMaxDynamicSharedMemorySize, SM_TOTAL);
        smem_set = 1;
    }

    gemm_mma_kernel<<<148, 256, SM_TOTAL>>>(x, W1, b1, N);

    int blocks = (E + 31) / 32;
    edge_kernel<<<blocks, 256>>>(ei, W2, b2, out, E, N);
}